// round 8
// baseline (speedup 1.0000x reference)
#include <cuda_runtime.h>
#include <cuda_bf16.h>
#include <math.h>
#include <stdint.h>

#define THREADS 256

// ---------------- scratch (device globals; no allocation allowed) ----------
__device__ float g_h1  [16u*128u*128u*64u];             // conv1 out NHWC (67MB)
__device__ float g_h2  [65536u*128u];                   // conv2 out NHWC
__device__ float g_feat[16384u*256u];                   // conv3 out (fp32 exact)
__device__ float g_d2  [16u*128u*128u*64u];             // deconv2 out NHWC fp32
__device__ float g_wp  [2097152u];                      // packed weights (8MB)
__device__ __nv_bfloat16 g_cbb[8192u*256u];             // codebook bf16
__device__ __nv_bfloat16 g_fb[16384u*256u];             // feat bf16
__device__ unsigned long long g_grp[16384u*256u];       // per-32-code group max keys
__device__ __nv_bfloat16 g_qh[16384u*256u];             // quantized hi
__device__ __nv_bfloat16 g_ql[16384u*256u];             // quantized lo
__device__ __nv_bfloat16 g_xh[16u*64u*64u*128u];        // deconv1 out hi
__device__ __nv_bfloat16 g_xl[16u*64u*64u*128u];        // deconv1 out lo

// ---------------- helpers ----------------------------------------------------
__device__ __forceinline__ uint32_t smem_u32(const void* p) {
    uint32_t a;
    asm("{ .reg .u64 t; cvta.to.shared.u64 t, %1; cvt.u32.u64 %0, t; }" : "=r"(a) : "l"(p));
    return a;
}
#define CP_ASYNC16(dst, src) \
    asm volatile("cp.async.cg.shared.global [%0], [%1], 16;" :: "r"(dst), "l"(src) : "memory")
#define CP_ASYNC16Z(dst, src, n) \
    asm volatile("cp.async.cg.shared.global [%0], [%1], 16, %2;" :: "r"(dst), "l"(src), "r"(n) : "memory")
#define CP_COMMIT() asm volatile("cp.async.commit_group;" ::: "memory")
#define CP_WAIT0()  asm volatile("cp.async.wait_group 0;" ::: "memory")

__device__ __forceinline__ unsigned ford(float f) {
    unsigned u = __float_as_uint(f);
    return (u & 0x80000000u) ? ~u : (u | 0x80000000u);
}
__device__ __forceinline__ float iford(unsigned e) {
    return (e & 0x80000000u) ? __uint_as_float(e ^ 0x80000000u) : __uint_as_float(~e);
}
__device__ __forceinline__ unsigned long long mkkey(float v, unsigned idx) {
    return ((unsigned long long)ford(v) << 32) | (0xFFFFFFFFu - idx);
}

#define MMA_BF16(ACC, A, B) \
    asm volatile("mma.sync.aligned.m16n8k16.row.col.f32.bf16.bf16.f32 " \
        "{%0,%1,%2,%3}, {%4,%5,%6,%7}, {%8,%9}, {%0,%1,%2,%3};" \
        : "+f"((ACC)[0]), "+f"((ACC)[1]), "+f"((ACC)[2]), "+f"((ACC)[3]) \
        : "r"((A)[0]), "r"((A)[1]), "r"((A)[2]), "r"((A)[3]), "r"((B)[0]), "r"((B)[1]))

// ---------------- prep device functions --------------------------------------
__device__ __forceinline__ void pack_w_conv_b(const float* __restrict__ w,
                                              float* __restrict__ Bp,
                                              int Ci, int Co, int gid)
{
    int k = gid / Co, co = gid % Co;
    int ci = k % Ci;
    int kidx = k / Ci;
    int kh = kidx >> 2, kw = kidx & 3;
    Bp[gid] = w[(((size_t)co * Ci + ci) * 4 + kh) * 4 + kw];
}

__device__ __forceinline__ void pack_w_deconv_b(const float* __restrict__ w,
                                                __nv_bfloat16* __restrict__ Bh,
                                                __nv_bfloat16* __restrict__ Bl,
                                                int Ci, int Co, int gid)
{
    int K = 4 * Ci;
    int cls = gid / (K * Co);
    int g2 = gid % (K * Co);
    int n = g2 / K, k = g2 % K;
    int ci = k % Ci;
    int kidx = k / Ci;
    int th = kidx >> 1, tw = kidx & 1;
    int kh = 2 * th + (cls >> 1);
    int kw = 2 * tw + (cls & 1);
    float v = w[(((size_t)n * Ci + ci) * 4 + kh) * 4 + kw];
    __nv_bfloat16 h = __float2bfloat16(v);
    Bh[gid] = h;
    Bl[gid] = __float2bfloat16(v - __bfloat162float(h));
}

// ---------------- conv1 + all prep work in one kernel ------------------------
__global__ void conv1_prep_k(const float* __restrict__ x, const float* __restrict__ w,
                             const float* __restrict__ b, float* __restrict__ y,
                             const float* __restrict__ ew2, float* __restrict__ wp2,
                             const float* __restrict__ ew3, float* __restrict__ wp3,
                             const float* __restrict__ cb, __nv_bfloat16* __restrict__ cbb,
                             const float* __restrict__ dw1, __nv_bfloat16* __restrict__ wh1,
                             __nv_bfloat16* __restrict__ wl1,
                             const float* __restrict__ dw2, __nv_bfloat16* __restrict__ wh2,
                             __nv_bfloat16* __restrict__ wl2)
{
    const int bid = blockIdx.x;
    const int tid = threadIdx.x;
    if (bid < 65536) {
        __shared__ float ws[64 * 48];
        for (int i = tid; i < 64 * 48; i += THREADS) ws[i] = w[i];
        __syncthreads();
        unsigned gid = bid * THREADS + tid;
        int co = gid & 63;
        int ow = (gid >> 6) & 127;
        int oh = (gid >> 13) & 127;
        int n  = gid >> 20;
        float acc = b[co];
        #pragma unroll
        for (int kh = 0; kh < 4; kh++) {
            int ih = 2 * oh + kh - 1;
            if ((unsigned)ih >= 256u) continue;
            #pragma unroll
            for (int kw = 0; kw < 4; kw++) {
                int iw = 2 * ow + kw - 1;
                if ((unsigned)iw >= 256u) continue;
                #pragma unroll
                for (int ci = 0; ci < 3; ci++) {
                    acc += x[((size_t)(n * 3 + ci) * 256 + ih) * 256 + iw]
                         * ws[co * 48 + ci * 16 + kh * 4 + kw];
                }
            }
        }
        y[gid] = fmaxf(acc, 0.f);
    } else if (bid < 65536 + 512) {
        int gid = (bid - 65536) * THREADS + tid;
        pack_w_conv_b(ew2, wp2, 64, 128, gid);
    } else if (bid < 65536 + 512 + 2048) {
        int gid = (bid - (65536 + 512)) * THREADS + tid;
        pack_w_conv_b(ew3, wp3, 128, 256, gid);
    } else if (bid < 65536 + 512 + 2048 + 2048) {
        unsigned i = (bid - (65536 + 512 + 2048)) * THREADS + tid;
        float4 v = reinterpret_cast<const float4*>(cb)[i];
        __nv_bfloat162* o = reinterpret_cast<__nv_bfloat162*>(cbb) + 2u * i;
        o[0] = __nv_bfloat162(__float2bfloat16(v.x), __float2bfloat16(v.y));
        o[1] = __nv_bfloat162(__float2bfloat16(v.z), __float2bfloat16(v.w));
    } else if (bid < 65536 + 512 + 2048 + 2048 + 2048) {
        int gid = (bid - (65536 + 512 + 2048 + 2048)) * THREADS + tid;
        pack_w_deconv_b(dw1, wh1, wl1, 256, 128, gid);
    } else {
        int gid = (bid - (65536 + 512 + 2048 + 2048 + 2048)) * THREADS + tid;
        pack_w_deconv_b(dw2, wh2, wl2, 128, 64, gid);
    }
}

// ---------------- implicit-im2col SGEMM (fp32, encoder) ----------------------
// MODE 0: out = relu(acc+bias); MODE 2: out fp32 + out2 bf16 (no relu)
// BM = 128 or 64 (k-summation order identical for both -> bit-exact results)
template<int LC, int LW, int MODE, int BM>
__global__ void __launch_bounds__(256, 2)
gemm_k(const float* __restrict__ Asrc, const float* __restrict__ B,
       int M, int N, int K,
       const float* __restrict__ bias,
       float* __restrict__ out, __nv_bfloat16* __restrict__ out2)
{
    constexpr int BK = 16, BN = 128, TN = 8, TM = BM / 16;
    constexpr unsigned C = 1u << LC;
    constexpr unsigned W = 1u << LW;
    __shared__ float As[BK][BM];
    __shared__ float Bs[BK][BN];
    int tid = threadIdx.x;
    int tx = tid & 15, ty = tid >> 4;
    int rowBase = blockIdx.y * BM;
    int colBase = blockIdx.x * BN;

    const int r = (BM == 128) ? (tid >> 1) : (tid >> 2);
    const unsigned row = rowBase + r;
    const unsigned cw = row & (W - 1);
    const unsigned rh = (row >> LW) & (W - 1);
    const unsigned n  = row >> (2 * LW);

    float acc[TM][TN];
    #pragma unroll
    for (int j = 0; j < TM; j++)
        #pragma unroll
        for (int i = 0; i < TN; i++) acc[j][i] = 0.f;

    for (int k0 = 0; k0 < K; k0 += BK) {
        #pragma unroll
        for (int t = 0; t < BM / 64; ++t) {
            int kq = (BM == 128) ? ((tid & 1) * 2 + t) : (tid & 3);
            int k = k0 + kq * 4;
            unsigned ci = (unsigned)k & (C - 1);
            int kidx = k >> LC;
            int kh = kidx >> 2, kw = kidx & 3;
            int ih = 2 * (int)rh + kh - 1, iw = 2 * (int)cw + kw - 1;
            float4 v = make_float4(0.f, 0.f, 0.f, 0.f);
            if ((unsigned)ih < 2 * W && (unsigned)iw < 2 * W)
                v = *reinterpret_cast<const float4*>(
                    Asrc + ((((size_t)n * 2 * W + ih) * 2 * W + iw) << LC) + ci);
            As[kq * 4 + 0][r] = v.x;
            As[kq * 4 + 1][r] = v.y;
            As[kq * 4 + 2][r] = v.z;
            As[kq * 4 + 3][r] = v.w;
        }
        #pragma unroll
        for (int t = 0; t < 2; ++t) {
            int idx = t * 256 + tid;
            int kk = idx >> 5;
            int c4 = idx & 31;
            float4 v = *reinterpret_cast<const float4*>(B + (size_t)(k0 + kk) * N + colBase + c4 * 4);
            *reinterpret_cast<float4*>(&Bs[kk][c4 * 4]) = v;
        }
        __syncthreads();
        #pragma unroll
        for (int k = 0; k < BK; ++k) {
            float a[TM];
            #pragma unroll
            for (int qq = 0; qq < TM / 4; qq++) {
                float4 av = *reinterpret_cast<const float4*>(&As[k][ty * TM + qq * 4]);
                a[qq * 4 + 0] = av.x; a[qq * 4 + 1] = av.y; a[qq * 4 + 2] = av.z; a[qq * 4 + 3] = av.w;
            }
            float b[TN];
            #pragma unroll
            for (int qq = 0; qq < 2; qq++) {
                float4 bv = *reinterpret_cast<const float4*>(&Bs[k][tx * TN + qq * 4]);
                b[qq * 4 + 0] = bv.x; b[qq * 4 + 1] = bv.y; b[qq * 4 + 2] = bv.z; b[qq * 4 + 3] = bv.w;
            }
            #pragma unroll
            for (int j = 0; j < TM; j++)
                #pragma unroll
                for (int i = 0; i < TN; i++)
                    acc[j][i] += a[j] * b[i];
        }
        __syncthreads();
    }

    #pragma unroll
    for (int j = 0; j < TM; j++) {
        int orow = rowBase + ty * TM + j;
        #pragma unroll
        for (int i = 0; i < TN; i++) {
            int col = colBase + tx * TN + i;
            float v = acc[j][i] + bias[col];
            if (MODE == 0) v = fmaxf(v, 0.f);
            out[(size_t)orow * N + col] = v;
            if (MODE == 2) out2[(size_t)orow * N + col] = __float2bfloat16(v);
        }
    }
}

// ---------------- deconv via split-bf16 HMMA, 64-row tiles -------------------
// 64-row M tile: acc = 2*NT*4 regs (32 or 16) -> no register spill at occ 2.
template<int LC, int LW, int NN, int WN, bool OUTSPLIT>
__global__ void __launch_bounds__(256, 2)
deconv_hmma_k(const __nv_bfloat16* __restrict__ Ahg, const __nv_bfloat16* __restrict__ Alg,
              const __nv_bfloat16* __restrict__ Bhg, const __nv_bfloat16* __restrict__ Blg,
              const float* __restrict__ bias,
              float* __restrict__ outF,
              __nv_bfloat16* __restrict__ outH, __nv_bfloat16* __restrict__ outL)
{
    constexpr int K = 4 << LC;
    constexpr int NKB = K / 32;
    constexpr unsigned C = 1u << LC, W = 1u << LW;
    constexpr int NT = WN / 8;
    constexpr int SZ_A = 64 * 40 * 2;          // 5120 B per (hi|lo)
    constexpr int SZ_B = NN * 40 * 2;
    constexpr int STG = 2 * SZ_A + 2 * SZ_B;
    extern __shared__ __align__(16) char dsm[];
    const uint32_t sB = smem_u32(dsm);
    const int tid = threadIdx.x, lane = tid & 31, warp = tid >> 5;
    const int wm = warp >> 2, wn = warp & 3;   // wm in {0,1}: 32-row halves
    const int mtBase = blockIdx.x * 64;
    const int z = blockIdx.z;
    const int ph = z >> 1, pw = z & 1;
    const __nv_bfloat16* BhC = Bhg + (size_t)z * NN * K;
    const __nv_bfloat16* BlC = Blg + (size_t)z * NN * K;

    float acc[2][NT][4];
    #pragma unroll
    for (int i = 0; i < 2; i++)
        #pragma unroll
        for (int j = 0; j < NT; j++)
            #pragma unroll
            for (int rr = 0; rr < 4; rr++) acc[i][j][rr] = 0.f;

    auto loadKB = [&](int kb, int buf) {
        int k0 = kb * 32;
        int kidx = k0 >> LC;
        int th = kidx >> 1, tw = kidx & 1;
        unsigned cib = (unsigned)k0 & (C - 1);
        uint32_t base = sB + buf * STG;
        // A: 64 rows x 32k x {h,l}: 512 cp.asyncs = 2/thread
        #pragma unroll
        for (int s = 0; s < 2; s++) {
            int t = s * 256 + tid;
            int rl = t >> 3, c4 = t & 3, hl = (t >> 2) & 1;
            unsigned grow = mtBase + rl;
            unsigned cc = grow & (W - 1), rr2 = (grow >> LW) & (W - 1), nn2 = grow >> (2 * LW);
            int ih = (int)rr2 + th - 1 + ph, iw = (int)cc + tw - 1 + pw;
            int inb = ((unsigned)ih < W && (unsigned)iw < W) ? 16 : 0;
            size_t so = ((((size_t)nn2 * W + (unsigned)ih) * W + (unsigned)iw) << LC) + cib + c4 * 8;
            const __nv_bfloat16* src = (hl ? Alg : Ahg) + (inb ? so : 0);
            uint32_t dst = base + (hl ? SZ_A : 0) + (uint32_t)(rl * 80 + c4 * 16);
            CP_ASYNC16Z(dst, src, inb);
        }
        // B: NN rows x 32k x {h,l}
        #pragma unroll
        for (int s = 0; s < NN / 32; s++) {
            int t = s * 256 + tid;
            int nl = t >> 3, c4 = t & 3, hl = (t >> 2) & 1;
            const __nv_bfloat16* src = (hl ? BlC : BhC) + (size_t)nl * K + k0 + c4 * 8;
            uint32_t dst = base + 2 * SZ_A + (hl ? SZ_B : 0) + (uint32_t)(nl * 80 + c4 * 16);
            CP_ASYNC16(dst, src);
        }
    };

    loadKB(0, 0);
    CP_COMMIT();
    int buf = 0;
    for (int kb = 0; kb < NKB; kb++) {
        CP_WAIT0();
        __syncthreads();
        if (kb + 1 < NKB) { loadKB(kb + 1, buf ^ 1); CP_COMMIT(); }
        uint32_t base = sB + buf * STG;
        #pragma unroll
        for (int km = 0; km < 2; km++) {
            uint32_t bh[NT][2], bl[NT][2];
            #pragma unroll
            for (int nt = 0; nt < NT; nt++) {
                uint32_t off = (uint32_t)(((wn * WN + nt * 8 + (lane & 7)) * 40
                               + km * 16 + ((lane >> 3) & 1) * 8) * 2);
                asm volatile("ldmatrix.sync.aligned.m8n8.x2.shared.b16 {%0,%1}, [%2];"
                             : "=r"(bh[nt][0]), "=r"(bh[nt][1]) : "r"(base + 2 * SZ_A + off));
                asm volatile("ldmatrix.sync.aligned.m8n8.x2.shared.b16 {%0,%1}, [%2];"
                             : "=r"(bl[nt][0]), "=r"(bl[nt][1]) : "r"(base + 2 * SZ_A + SZ_B + off));
            }
            #pragma unroll
            for (int mt = 0; mt < 2; mt++) {
                uint32_t ah[4], al[4];
                uint32_t off = (uint32_t)(((wm * 32 + mt * 16 + (lane & 15)) * 40
                               + km * 16 + (lane >> 4) * 8) * 2);
                asm volatile("ldmatrix.sync.aligned.m8n8.x4.shared.b16 {%0,%1,%2,%3}, [%4];"
                             : "=r"(ah[0]), "=r"(ah[1]), "=r"(ah[2]), "=r"(ah[3]) : "r"(base + off));
                asm volatile("ldmatrix.sync.aligned.m8n8.x4.shared.b16 {%0,%1,%2,%3}, [%4];"
                             : "=r"(al[0]), "=r"(al[1]), "=r"(al[2]), "=r"(al[3]) : "r"(base + SZ_A + off));
                #pragma unroll
                for (int nt = 0; nt < NT; nt++) {
                    MMA_BF16(acc[mt][nt], ah, bh[nt]);
                    MMA_BF16(acc[mt][nt], al, bh[nt]);
                    MMA_BF16(acc[mt][nt], ah, bl[nt]);
                }
            }
        }
        __syncthreads();
        buf ^= 1;
    }

    const int gr = lane >> 2, gc = (lane & 3) * 2;
    #pragma unroll
    for (int mt = 0; mt < 2; mt++) {
        unsigned row0 = mtBase + wm * 32 + mt * 16 + gr;
        unsigned row1 = row0 + 8;
        unsigned c0 = row0 & (W - 1), r0 = (row0 >> LW) & (W - 1), n0 = row0 >> (2 * LW);
        unsigned c1 = row1 & (W - 1), r1 = (row1 >> LW) & (W - 1), n1 = row1 >> (2 * LW);
        size_t base0 = ((size_t)(n0 * 2 * W + 2 * r0 + ph) * 2 * W + (2 * c0 + pw)) * NN;
        size_t base1 = ((size_t)(n1 * 2 * W + 2 * r1 + ph) * 2 * W + (2 * c1 + pw)) * NN;
        #pragma unroll
        for (int nt = 0; nt < NT; nt++) {
            int col = wn * WN + nt * 8 + gc;
            float b0 = bias[col], b1 = bias[col + 1];
            float v00 = fmaxf(acc[mt][nt][0] + b0, 0.f), v01 = fmaxf(acc[mt][nt][1] + b1, 0.f);
            float v10 = fmaxf(acc[mt][nt][2] + b0, 0.f), v11 = fmaxf(acc[mt][nt][3] + b1, 0.f);
            if (OUTSPLIT) {
                __nv_bfloat162 h0 = __floats2bfloat162_rn(v00, v01);
                __nv_bfloat162 h1 = __floats2bfloat162_rn(v10, v11);
                __nv_bfloat162 l0 = __floats2bfloat162_rn(v00 - __low2float(h0), v01 - __high2float(h0));
                __nv_bfloat162 l1 = __floats2bfloat162_rn(v10 - __low2float(h1), v11 - __high2float(h1));
                *reinterpret_cast<__nv_bfloat162*>(outH + base0 + col) = h0;
                *reinterpret_cast<__nv_bfloat162*>(outL + base0 + col) = l0;
                *reinterpret_cast<__nv_bfloat162*>(outH + base1 + col) = h1;
                *reinterpret_cast<__nv_bfloat162*>(outL + base1 + col) = l1;
            } else {
                *reinterpret_cast<float2*>(outF + base0 + col) = make_float2(v00, v01);
                *reinterpret_cast<float2*>(outF + base1 + col) = make_float2(v10, v11);
            }
        }
    }
}

// ---------------- scores HMMA with fused per-32-code group max ---------------
__global__ void __launch_bounds__(256, 2)
scores_hmma_k(const __nv_bfloat16* __restrict__ featb,
              const __nv_bfloat16* __restrict__ cbb,
              unsigned long long* __restrict__ grp)
{
    constexpr int LDS = 40;
    __shared__ __align__(16) __nv_bfloat16 As[2][128][LDS];
    __shared__ __align__(16) __nv_bfloat16 Bs[2][128][LDS];
    const int tid = threadIdx.x;
    const int lane = tid & 31, warp = tid >> 5;
    const int wm = warp >> 2, wn = warp & 3;
    const int mtBase = blockIdx.y * 128, ntBase = blockIdx.x * 128;
    const uint32_t aSm = smem_u32(As), bSm = smem_u32(Bs);

    float acc[4][4][4];
    #pragma unroll
    for (int i = 0; i < 4; i++)
        #pragma unroll
        for (int j = 0; j < 4; j++)
            #pragma unroll
            for (int rr = 0; rr < 4; rr++) acc[i][j][rr] = 0.f;

    auto loadTiles = [&](int kt, int buf) {
        int k0 = kt * 32;
        #pragma unroll
        for (int s = 0; s < 2; s++) {
            int idx = s * 256 + tid;
            int row = idx >> 2, c = idx & 3;
            const __nv_bfloat16* srcA = featb + (size_t)(mtBase + row) * 256 + k0 + c * 8;
            const __nv_bfloat16* srcB = cbb   + (size_t)(ntBase + row) * 256 + k0 + c * 8;
            uint32_t da = aSm + (uint32_t)(((buf * 128 + row) * LDS + c * 8) * 2);
            uint32_t db = bSm + (uint32_t)(((buf * 128 + row) * LDS + c * 8) * 2);
            CP_ASYNC16(da, srcA);
            CP_ASYNC16(db, srcB);
        }
    };

    loadTiles(0, 0);
    CP_COMMIT();

    int buf = 0;
    for (int kt = 0; kt < 8; kt++) {
        CP_WAIT0();
        __syncthreads();
        if (kt < 7) { loadTiles(kt + 1, buf ^ 1); CP_COMMIT(); }

        #pragma unroll
        for (int km = 0; km < 2; km++) {
            uint32_t a[4][4], b[4][2];
            #pragma unroll
            for (int mt = 0; mt < 4; mt++) {
                uint32_t addr = aSm + (uint32_t)((((buf * 128 + wm * 64 + mt * 16 + (lane & 15)) * LDS)
                                + km * 16 + ((lane >> 4) * 8)) * 2);
                asm volatile("ldmatrix.sync.aligned.m8n8.x4.shared.b16 {%0,%1,%2,%3}, [%4];"
                             : "=r"(a[mt][0]), "=r"(a[mt][1]), "=r"(a[mt][2]), "=r"(a[mt][3])
                             : "r"(addr));
            }
            #pragma unroll
            for (int nt = 0; nt < 4; nt++) {
                uint32_t addr = bSm + (uint32_t)((((buf * 128 + wn * 32 + nt * 8 + (lane & 7)) * LDS)
                                + km * 16 + (((lane >> 3) & 1) * 8)) * 2);
                asm volatile("ldmatrix.sync.aligned.m8n8.x2.shared.b16 {%0,%1}, [%2];"
                             : "=r"(b[nt][0]), "=r"(b[nt][1]) : "r"(addr));
            }
            #pragma unroll
            for (int mt = 0; mt < 4; mt++)
                #pragma unroll
                for (int nt = 0; nt < 4; nt++)
                    MMA_BF16(acc[mt][nt], a[mt], b[nt]);
        }
        __syncthreads();
        buf ^= 1;
    }

    const int g = blockIdx.x * 4 + wn;
    const int gc = (lane & 3) * 2;
    #pragma unroll
    for (int mt = 0; mt < 4; mt++) {
        unsigned long long k0 = 0ull, k1 = 0ull;
        #pragma unroll
        for (int nt = 0; nt < 4; nt++) {
            unsigned col = (unsigned)(ntBase + wn * 32 + nt * 8 + gc);
            unsigned long long t;
            t = mkkey(acc[mt][nt][0], col);     if (t > k0) k0 = t;
            t = mkkey(acc[mt][nt][1], col + 1); if (t > k0) k0 = t;
            t = mkkey(acc[mt][nt][2], col);     if (t > k1) k1 = t;
            t = mkkey(acc[mt][nt][3], col + 1); if (t > k1) k1 = t;
        }
        #pragma unroll
        for (int m = 1; m <= 2; m <<= 1) {
            unsigned long long o0 = __shfl_xor_sync(0xffffffffu, k0, m);
            unsigned long long o1 = __shfl_xor_sync(0xffffffffu, k1, m);
            if (o0 > k0) k0 = o0;
            if (o1 > k1) k1 = o1;
        }
        if ((lane & 3) == 0) {
            unsigned row0 = mtBase + wm * 64 + mt * 16 + (lane >> 2);
            grp[(size_t)row0 * 256 + g] = k0;
            grp[(size_t)(row0 + 8) * 256 + g] = k1;
        }
    }
}

// ---------------- rescue: exact fp32 argmax over candidate groups ------------
__global__ void __launch_bounds__(256)
rescue_k(const unsigned long long* __restrict__ grp, const float* __restrict__ feat,
         const float* __restrict__ cb,
         __nv_bfloat16* __restrict__ qh, __nv_bfloat16* __restrict__ ql,
         float* __restrict__ idx_out)
{
    __shared__ float fsh[256];
    __shared__ unsigned long long gk[256];
    __shared__ unsigned long long wmax[8];
    __shared__ float wsum[8];
    __shared__ unsigned long long bestk;
    __shared__ float thr_s;
    const int row = blockIdx.x, tid = threadIdx.x;
    const int lane = tid & 31, wid = tid >> 5;

    float fv = feat[(size_t)row * 256 + tid];
    fsh[tid] = fv;
    unsigned long long k = grp[(size_t)row * 256 + tid];
    gk[tid] = k;
    float ssq = fv * fv;
    #pragma unroll
    for (int m = 16; m; m >>= 1) {
        ssq += __shfl_xor_sync(0xffffffffu, ssq, m);
        unsigned long long o = __shfl_xor_sync(0xffffffffu, k, m);
        if (o > k) k = o;
    }
    if (lane == 0) { wsum[wid] = ssq; wmax[wid] = k; }
    __syncthreads();
    if (tid == 0) {
        float s = 0.f;
        unsigned long long g = 0ull;
        #pragma unroll
        for (int i = 0; i < 8; i++) { s += wsum[i]; if (wmax[i] > g) g = wmax[i]; }
        thr_s = iford((unsigned)(g >> 32)) - 0.1f * sqrtf(s);
        bestk = 0ull;
    }
    __syncthreads();

    unsigned long long lb = 0ull;
    for (int g = wid; g < 256; g += 8) {
        if (iford((unsigned)(gk[g] >> 32)) < thr_s) continue;
        #pragma unroll 1
        for (int cc = 0; cc < 32; cc++) {
            unsigned code = (unsigned)(g * 32 + cc);
            const float4* crow = reinterpret_cast<const float4*>(cb + (size_t)code * 256);
            const float4* frow = reinterpret_cast<const float4*>(fsh);
            float a = 0.f;
            #pragma unroll
            for (int j = 0; j < 2; j++) {
                float4 cv = crow[lane * 2 + j];
                float4 fq = frow[lane * 2 + j];
                a += fq.x * cv.x + fq.y * cv.y + fq.z * cv.z + fq.w * cv.w;
            }
            #pragma unroll
            for (int m = 16; m; m >>= 1) a += __shfl_xor_sync(0xffffffffu, a, m);
            if (lane == 0) {
                unsigned long long kk = mkkey(a, code);
                if (kk > lb) lb = kk;
            }
        }
    }
    if (lane == 0 && lb) atomicMax(&bestk, lb);
    __syncthreads();

    unsigned code = 0xFFFFFFFFu - (unsigned)(bestk & 0xFFFFFFFFull);
    float v = cb[(size_t)code * 256 + tid];
    __nv_bfloat16 h = __float2bfloat16(v);
    qh[(size_t)row * 256 + tid] = h;
    ql[(size_t)row * 256 + tid] = __float2bfloat16(v - __bfloat162float(h));
    if (tid == 0 && idx_out) idx_out[row] = (float)code;
}

// ---------------- deconv3: direct, Cout=3, NHWC in -> NCHW out --------------
__global__ void deconv3_k(const float* __restrict__ in, const float* __restrict__ w,
                          const float* __restrict__ b, float* __restrict__ out)
{
    __shared__ float ws[3 * 64 * 16];
    for (int i = threadIdx.x; i < 3072; i += THREADS) ws[i] = w[i];
    __syncthreads();
    int gid = blockIdx.x * THREADS + threadIdx.x;
    int ow = gid & 255;
    int oh = (gid >> 8) & 255;
    int n  = gid >> 16;
    int ph = oh & 1, pw = ow & 1;
    int r = oh >> 1, c = ow >> 1;
    float a0 = b[0], a1 = b[1], a2 = b[2];
    #pragma unroll
    for (int th = 0; th < 2; th++) {
        int ih = r + th - 1 + ph;
        if ((unsigned)ih >= 128u) continue;
        int kh = 2 * th + ph;
        #pragma unroll
        for (int tw = 0; tw < 2; tw++) {
            int iw = c + tw - 1 + pw;
            if ((unsigned)iw >= 128u) continue;
            int kw = 2 * tw + pw;
            const float* xp = in + ((size_t)(n * 128 + ih) * 128 + iw) * 64;
            int wo = kh * 4 + kw;
            #pragma unroll
            for (int c4 = 0; c4 < 16; c4++) {
                float4 xv = *reinterpret_cast<const float4*>(xp + c4 * 4);
                int ci = c4 * 4;
                a0 += xv.x * ws[(0 * 64 + ci) * 16 + wo] + xv.y * ws[(0 * 64 + ci + 1) * 16 + wo]
                    + xv.z * ws[(0 * 64 + ci + 2) * 16 + wo] + xv.w * ws[(0 * 64 + ci + 3) * 16 + wo];
                a1 += xv.x * ws[(1 * 64 + ci) * 16 + wo] + xv.y * ws[(1 * 64 + ci + 1) * 16 + wo]
                    + xv.z * ws[(1 * 64 + ci + 2) * 16 + wo] + xv.w * ws[(1 * 64 + ci + 3) * 16 + wo];
                a2 += xv.x * ws[(2 * 64 + ci) * 16 + wo] + xv.y * ws[(2 * 64 + ci + 1) * 16 + wo]
                    + xv.z * ws[(2 * 64 + ci + 2) * 16 + wo] + xv.w * ws[(2 * 64 + ci + 3) * 16 + wo];
            }
        }
    }
    size_t p = (size_t)n * 3 * 65536 + (size_t)oh * 256 + ow;
    out[p] = a0;
    out[p + 65536] = a1;
    out[p + 2 * 65536] = a2;
}

// ---------------------------------------------------------------------------
extern "C" void kernel_launch(void* const* d_in, const int* in_sizes, int n_in,
                              void* d_out, int out_size)
{
    const float* x   = (const float*)d_in[0];
    const float* ew1 = (const float*)d_in[1];
    const float* eb1 = (const float*)d_in[2];
    const float* ew2 = (const float*)d_in[3];
    const float* eb2 = (const float*)d_in[4];
    const float* ew3 = (const float*)d_in[5];
    const float* eb3 = (const float*)d_in[6];
    const float* cb  = (const float*)d_in[7];
    const float* dw1 = (const float*)d_in[8];
    const float* db1 = (const float*)d_in[9];
    const float* dw2 = (const float*)d_in[10];
    const float* db2 = (const float*)d_in[11];
    const float* dw3 = (const float*)d_in[12];
    const float* db3 = (const float*)d_in[13];
    float* out = (float*)d_out;

    float *h1, *h2, *feat, *d2, *wp;
    __nv_bfloat16 *cbb, *fb, *qh, *ql, *xh, *xl;
    unsigned long long* grp;
    cudaGetSymbolAddress((void**)&h1,   g_h1);
    cudaGetSymbolAddress((void**)&h2,   g_h2);
    cudaGetSymbolAddress((void**)&feat, g_feat);
    cudaGetSymbolAddress((void**)&d2,   g_d2);
    cudaGetSymbolAddress((void**)&wp,   g_wp);
    cudaGetSymbolAddress((void**)&cbb,  g_cbb);
    cudaGetSymbolAddress((void**)&fb,   g_fb);
    cudaGetSymbolAddress((void**)&grp,  g_grp);
    cudaGetSymbolAddress((void**)&qh,   g_qh);
    cudaGetSymbolAddress((void**)&ql,   g_ql);
    cudaGetSymbolAddress((void**)&xh,   g_xh);
    cudaGetSymbolAddress((void**)&xl,   g_xl);

    float* wp3 = wp;                                           // 524288 f
    float* wp2 = wp + 524288;                                  // 131072 f
    __nv_bfloat16* wh1 = (__nv_bfloat16*)(wp + 655360);        // 524288 bf
    __nv_bfloat16* wl1 = (__nv_bfloat16*)(wp + 917504);        // 524288 bf
    __nv_bfloat16* wh2 = (__nv_bfloat16*)(wp + 1179648);       // 131072 bf
    __nv_bfloat16* wl2 = (__nv_bfloat16*)(wp + 1245184);       // 131072 bf

    const int RECON = 16 * 3 * 256 * 256;
    float* idx_out = (out_size >= RECON + 16384) ? (out + RECON) : nullptr;

    // 1: conv1 + ALL prep
    conv1_prep_k<<<65536 + 512 + 2048 + 2048 + 2048 + 512, THREADS>>>(
        x, ew1, eb1, h1, ew2, wp2, ew3, wp3, cb, cbb, dw1, wh1, wl1, dw2, wh2, wl2);

    // 2-3: encoder GEMMs (fp32 exact; BM=64 for gemm3 doubles CTA count)
    gemm_k<6, 6, 0, 128><<<dim3(1, 512), THREADS>>>(h1, wp2, 65536, 128, 1024, eb2, h2, nullptr);
    gemm_k<7, 5, 2, 64><<<dim3(2, 256), THREADS>>>(h2, wp3, 16384, 256, 2048, eb3, feat, fb);

    // 4-5: quantize
    scores_hmma_k<<<dim3(64, 128), THREADS>>>(fb, cbb, grp);
    rescue_k<<<16384, THREADS>>>(grp, feat, cb, qh, ql, idx_out);

    // 6-7: decoder split-bf16 HMMA deconvs (64-row tiles, no spill)
    {
        constexpr int SMEM1 = 2 * (2 * 64 * 40 * 2 + 2 * 128 * 40 * 2);    // 61440
        cudaFuncSetAttribute((const void*)deconv_hmma_k<8, 5, 128, 32, true>,
                             cudaFuncAttributeMaxDynamicSharedMemorySize, SMEM1);
        deconv_hmma_k<8, 5, 128, 32, true><<<dim3(256, 1, 4), THREADS, SMEM1>>>(
            qh, ql, wh1, wl1, db1, nullptr, xh, xl);
    }
    {
        constexpr int SMEM2 = 2 * (2 * 64 * 40 * 2 + 2 * 64 * 40 * 2);     // 40960
        cudaFuncSetAttribute((const void*)deconv_hmma_k<7, 6, 64, 16, false>,
                             cudaFuncAttributeMaxDynamicSharedMemorySize, SMEM2);
        deconv_hmma_k<7, 6, 64, 16, false><<<dim3(1024, 1, 4), THREADS, SMEM2>>>(
            xh, xl, wh2, wl2, db2, d2, nullptr, nullptr);
    }

    // 8: final deconv
    deconv3_k<<<4096, THREADS>>>(d2, dw3, db3, out);
}

// round 10
// speedup vs baseline: 1.4523x; 1.4523x over previous
#include <cuda_runtime.h>
#include <cuda_bf16.h>
#include <math.h>
#include <stdint.h>

#define THREADS 256

// ---------------- scratch (device globals; no allocation allowed) ----------
__device__ float g_h1  [16u*128u*128u*64u];             // conv1 out NHWC (67MB)
__device__ float g_h2  [65536u*128u];                   // conv2 out NHWC
__device__ float g_feat[16384u*256u];                   // conv3 out (fp32 exact)
__device__ float g_d2  [16u*128u*128u*64u];             // deconv2 out NHWC fp32
__device__ float g_wp  [2097152u];                      // packed weights (8MB)
__device__ __nv_bfloat16 g_cbb[8192u*256u];             // codebook bf16
__device__ __nv_bfloat16 g_fb[16384u*256u];             // feat bf16
__device__ unsigned long long g_grp[16384u*256u];       // per-32-code group max keys
__device__ __nv_bfloat16 g_qh[16384u*256u];             // quantized hi
__device__ __nv_bfloat16 g_ql[16384u*256u];             // quantized lo
__device__ __nv_bfloat16 g_xh[16u*64u*64u*128u];        // deconv1 out hi
__device__ __nv_bfloat16 g_xl[16u*64u*64u*128u];        // deconv1 out lo

// ---------------- helpers ----------------------------------------------------
__device__ __forceinline__ uint32_t smem_u32(const void* p) {
    uint32_t a;
    asm("{ .reg .u64 t; cvta.to.shared.u64 t, %1; cvt.u32.u64 %0, t; }" : "=r"(a) : "l"(p));
    return a;
}
#define CP_ASYNC16(dst, src) \
    asm volatile("cp.async.cg.shared.global [%0], [%1], 16;" :: "r"(dst), "l"(src) : "memory")
#define CP_ASYNC16Z(dst, src, n) \
    asm volatile("cp.async.cg.shared.global [%0], [%1], 16, %2;" :: "r"(dst), "l"(src), "r"(n) : "memory")
#define CP_COMMIT() asm volatile("cp.async.commit_group;" ::: "memory")
#define CP_WAIT0()  asm volatile("cp.async.wait_group 0;" ::: "memory")

__device__ __forceinline__ unsigned ford(float f) {
    unsigned u = __float_as_uint(f);
    return (u & 0x80000000u) ? ~u : (u | 0x80000000u);
}
__device__ __forceinline__ float iford(unsigned e) {
    return (e & 0x80000000u) ? __uint_as_float(e ^ 0x80000000u) : __uint_as_float(~e);
}
__device__ __forceinline__ unsigned long long mkkey(float v, unsigned idx) {
    return ((unsigned long long)ford(v) << 32) | (0xFFFFFFFFu - idx);
}

#define MMA_BF16(ACC, A, B) \
    asm volatile("mma.sync.aligned.m16n8k16.row.col.f32.bf16.bf16.f32 " \
        "{%0,%1,%2,%3}, {%4,%5,%6,%7}, {%8,%9}, {%0,%1,%2,%3};" \
        : "+f"((ACC)[0]), "+f"((ACC)[1]), "+f"((ACC)[2]), "+f"((ACC)[3]) \
        : "r"((A)[0]), "r"((A)[1]), "r"((A)[2]), "r"((A)[3]), "r"((B)[0]), "r"((B)[1]))

// ---------------- prep device functions --------------------------------------
__device__ __forceinline__ void pack_w_conv_b(const float* __restrict__ w,
                                              float* __restrict__ Bp,
                                              int Ci, int Co, int gid)
{
    int k = gid / Co, co = gid % Co;
    int ci = k % Ci;
    int kidx = k / Ci;
    int kh = kidx >> 2, kw = kidx & 3;
    Bp[gid] = w[(((size_t)co * Ci + ci) * 4 + kh) * 4 + kw];
}

__device__ __forceinline__ void pack_w_deconv_b(const float* __restrict__ w,
                                                __nv_bfloat16* __restrict__ Bh,
                                                __nv_bfloat16* __restrict__ Bl,
                                                int Ci, int Co, int gid)
{
    int K = 4 * Ci;
    int cls = gid / (K * Co);
    int g2 = gid % (K * Co);
    int n = g2 / K, k = g2 % K;
    int ci = k % Ci;
    int kidx = k / Ci;
    int th = kidx >> 1, tw = kidx & 1;
    int kh = 2 * th + (cls >> 1);
    int kw = 2 * tw + (cls & 1);
    float v = w[(((size_t)n * Ci + ci) * 4 + kh) * 4 + kw];
    __nv_bfloat16 h = __float2bfloat16(v);
    Bh[gid] = h;
    Bl[gid] = __float2bfloat16(v - __bfloat162float(h));
}

// ---------------- conv1 + all prep work in one kernel ------------------------
// conv1 weights in smem TRANSPOSED: ws[idx*64 + co] -> conflict-free LDS
// (old layout ws[co*48+idx] was a 16-way bank conflict on every load).
__global__ void conv1_prep_k(const float* __restrict__ x, const float* __restrict__ w,
                             const float* __restrict__ b, float* __restrict__ y,
                             const float* __restrict__ ew2, float* __restrict__ wp2,
                             const float* __restrict__ ew3, float* __restrict__ wp3,
                             const float* __restrict__ cb, __nv_bfloat16* __restrict__ cbb,
                             const float* __restrict__ dw1, __nv_bfloat16* __restrict__ wh1,
                             __nv_bfloat16* __restrict__ wl1,
                             const float* __restrict__ dw2, __nv_bfloat16* __restrict__ wh2,
                             __nv_bfloat16* __restrict__ wl2)
{
    const int bid = blockIdx.x;
    const int tid = threadIdx.x;
    if (bid < 65536) {
        __shared__ float ws[48 * 64];          // [idx][co]
        for (int j = tid; j < 48 * 64; j += THREADS) {
            int idx = j >> 6, co = j & 63;
            ws[j] = w[co * 48 + idx];
        }
        __syncthreads();
        unsigned gid = bid * THREADS + tid;
        int co = gid & 63;
        int ow = (gid >> 6) & 127;
        int oh = (gid >> 13) & 127;
        int n  = gid >> 20;
        float acc = b[co];
        #pragma unroll
        for (int kh = 0; kh < 4; kh++) {
            int ih = 2 * oh + kh - 1;
            if ((unsigned)ih >= 256u) continue;
            #pragma unroll
            for (int kw = 0; kw < 4; kw++) {
                int iw = 2 * ow + kw - 1;
                if ((unsigned)iw >= 256u) continue;
                #pragma unroll
                for (int ci = 0; ci < 3; ci++) {
                    acc += x[((size_t)(n * 3 + ci) * 256 + ih) * 256 + iw]
                         * ws[(ci * 16 + kh * 4 + kw) * 64 + co];
                }
            }
        }
        y[gid] = fmaxf(acc, 0.f);
    } else if (bid < 65536 + 512) {
        int gid = (bid - 65536) * THREADS + tid;
        pack_w_conv_b(ew2, wp2, 64, 128, gid);
    } else if (bid < 65536 + 512 + 2048) {
        int gid = (bid - (65536 + 512)) * THREADS + tid;
        pack_w_conv_b(ew3, wp3, 128, 256, gid);
    } else if (bid < 65536 + 512 + 2048 + 2048) {
        unsigned i = (bid - (65536 + 512 + 2048)) * THREADS + tid;
        float4 v = reinterpret_cast<const float4*>(cb)[i];
        __nv_bfloat162* o = reinterpret_cast<__nv_bfloat162*>(cbb) + 2u * i;
        o[0] = __nv_bfloat162(__float2bfloat16(v.x), __float2bfloat16(v.y));
        o[1] = __nv_bfloat162(__float2bfloat16(v.z), __float2bfloat16(v.w));
    } else if (bid < 65536 + 512 + 2048 + 2048 + 2048) {
        int gid = (bid - (65536 + 512 + 2048 + 2048)) * THREADS + tid;
        pack_w_deconv_b(dw1, wh1, wl1, 256, 128, gid);
    } else {
        int gid = (bid - (65536 + 512 + 2048 + 2048 + 2048)) * THREADS + tid;
        pack_w_deconv_b(dw2, wh2, wl2, 128, 64, gid);
    }
}

// ---------------- implicit-im2col SGEMM (fp32, encoder) ----------------------
// MODE 0: out = relu(acc+bias); MODE 2: out fp32 + out2 bf16 (no relu)
template<int LC, int LW, int MODE>
__global__ void __launch_bounds__(256, 2)
gemm_k(const float* __restrict__ Asrc, const float* __restrict__ B,
       int M, int N, int K,
       const float* __restrict__ bias,
       float* __restrict__ out, __nv_bfloat16* __restrict__ out2)
{
    constexpr int BM = 128, BK = 16, BN = 128, TM = 8, TN = 8;
    constexpr unsigned C = 1u << LC;
    constexpr unsigned W = 1u << LW;
    __shared__ float As[BK][BM];
    __shared__ float Bs[BK][BN];
    int tid = threadIdx.x;
    int tx = tid & 15, ty = tid >> 4;
    int rowBase = blockIdx.y * BM;
    int colBase = blockIdx.x * BN;

    const int r = tid >> 1;
    const unsigned row = rowBase + r;
    const unsigned cw = row & (W - 1);
    const unsigned rh = (row >> LW) & (W - 1);
    const unsigned n  = row >> (2 * LW);

    float acc[TM][TN];
    #pragma unroll
    for (int j = 0; j < TM; j++)
        #pragma unroll
        for (int i = 0; i < TN; i++) acc[j][i] = 0.f;

    for (int k0 = 0; k0 < K; k0 += BK) {
        #pragma unroll
        for (int t = 0; t < 2; ++t) {
            int kq = (tid & 1) * 2 + t;
            int k = k0 + kq * 4;
            unsigned ci = (unsigned)k & (C - 1);
            int kidx = k >> LC;
            int kh = kidx >> 2, kw = kidx & 3;
            int ih = 2 * (int)rh + kh - 1, iw = 2 * (int)cw + kw - 1;
            float4 v = make_float4(0.f, 0.f, 0.f, 0.f);
            if ((unsigned)ih < 2 * W && (unsigned)iw < 2 * W)
                v = *reinterpret_cast<const float4*>(
                    Asrc + ((((size_t)n * 2 * W + ih) * 2 * W + iw) << LC) + ci);
            As[kq * 4 + 0][r] = v.x;
            As[kq * 4 + 1][r] = v.y;
            As[kq * 4 + 2][r] = v.z;
            As[kq * 4 + 3][r] = v.w;
        }
        #pragma unroll
        for (int t = 0; t < 2; ++t) {
            int idx = t * 256 + tid;
            int kk = idx >> 5;
            int c4 = idx & 31;
            float4 v = *reinterpret_cast<const float4*>(B + (size_t)(k0 + kk) * N + colBase + c4 * 4);
            *reinterpret_cast<float4*>(&Bs[kk][c4 * 4]) = v;
        }
        __syncthreads();
        #pragma unroll
        for (int k = 0; k < BK; ++k) {
            float4 a0 = *reinterpret_cast<const float4*>(&As[k][ty * TM]);
            float4 a1 = *reinterpret_cast<const float4*>(&As[k][ty * TM + 4]);
            float a[TM] = {a0.x, a0.y, a0.z, a0.w, a1.x, a1.y, a1.z, a1.w};
            float b[TN];
            #pragma unroll
            for (int qq = 0; qq < 2; qq++) {
                float4 bv = *reinterpret_cast<const float4*>(&Bs[k][tx * TN + qq * 4]);
                b[qq * 4 + 0] = bv.x; b[qq * 4 + 1] = bv.y; b[qq * 4 + 2] = bv.z; b[qq * 4 + 3] = bv.w;
            }
            #pragma unroll
            for (int j = 0; j < TM; j++)
                #pragma unroll
                for (int i = 0; i < TN; i++)
                    acc[j][i] += a[j] * b[i];
        }
        __syncthreads();
    }

    #pragma unroll
    for (int j = 0; j < TM; j++) {
        int orow = rowBase + ty * TM + j;
        #pragma unroll
        for (int i = 0; i < TN; i++) {
            int col = colBase + tx * TN + i;
            float v = acc[j][i] + bias[col];
            if (MODE == 0) v = fmaxf(v, 0.f);
            out[(size_t)orow * N + col] = v;
            if (MODE == 2) out2[(size_t)orow * N + col] = __float2bfloat16(v);
        }
    }
}

// ---------------- deconv via split-bf16 HMMA, double-buffered (128-row) ------
template<int LC, int LW, int NN, int WN, bool OUTSPLIT>
__global__ void __launch_bounds__(256, 2)
deconv_hmma_k(const __nv_bfloat16* __restrict__ Ahg, const __nv_bfloat16* __restrict__ Alg,
              const __nv_bfloat16* __restrict__ Bhg, const __nv_bfloat16* __restrict__ Blg,
              const float* __restrict__ bias,
              float* __restrict__ outF,
              __nv_bfloat16* __restrict__ outH, __nv_bfloat16* __restrict__ outL)
{
    constexpr int K = 4 << LC;
    constexpr int NKB = K / 32;
    constexpr unsigned C = 1u << LC, W = 1u << LW;
    constexpr int NT = WN / 8;
    constexpr int SZ_A = 128 * 40 * 2;
    constexpr int SZ_B = NN * 40 * 2;
    constexpr int STG = 2 * SZ_A + 2 * SZ_B;
    extern __shared__ __align__(16) char dsm[];
    const uint32_t sB = smem_u32(dsm);
    const int tid = threadIdx.x, lane = tid & 31, warp = tid >> 5;
    const int wm = warp >> 2, wn = warp & 3;
    const int mtBase = blockIdx.x * 128;
    const int z = blockIdx.z;
    const int ph = z >> 1, pw = z & 1;
    const __nv_bfloat16* BhC = Bhg + (size_t)z * NN * K;
    const __nv_bfloat16* BlC = Blg + (size_t)z * NN * K;

    float acc[4][NT][4];
    #pragma unroll
    for (int i = 0; i < 4; i++)
        #pragma unroll
        for (int j = 0; j < NT; j++)
            #pragma unroll
            for (int rr = 0; rr < 4; rr++) acc[i][j][rr] = 0.f;

    auto loadKB = [&](int kb, int buf) {
        int k0 = kb * 32;
        int kidx = k0 >> LC;
        int th = kidx >> 1, tw = kidx & 1;
        unsigned cib = (unsigned)k0 & (C - 1);
        uint32_t base = sB + buf * STG;
        #pragma unroll
        for (int s = 0; s < 4; s++) {
            int t = s * 256 + tid;
            int rl = t >> 3, c4 = t & 3, hl = (t >> 2) & 1;
            unsigned grow = mtBase + rl;
            unsigned cc = grow & (W - 1), rr2 = (grow >> LW) & (W - 1), nn2 = grow >> (2 * LW);
            int ih = (int)rr2 + th - 1 + ph, iw = (int)cc + tw - 1 + pw;
            int inb = ((unsigned)ih < W && (unsigned)iw < W) ? 16 : 0;
            size_t so = ((((size_t)nn2 * W + (unsigned)ih) * W + (unsigned)iw) << LC) + cib + c4 * 8;
            const __nv_bfloat16* src = (hl ? Alg : Ahg) + (inb ? so : 0);
            uint32_t dst = base + (hl ? SZ_A : 0) + (uint32_t)(rl * 80 + c4 * 16);
            CP_ASYNC16Z(dst, src, inb);
        }
        #pragma unroll
        for (int s = 0; s < NN / 32; s++) {
            int t = s * 256 + tid;
            int nl = t >> 3, c4 = t & 3, hl = (t >> 2) & 1;
            const __nv_bfloat16* src = (hl ? BlC : BhC) + (size_t)nl * K + k0 + c4 * 8;
            uint32_t dst = base + 2 * SZ_A + (hl ? SZ_B : 0) + (uint32_t)(nl * 80 + c4 * 16);
            CP_ASYNC16(dst, src);
        }
    };

    loadKB(0, 0);
    CP_COMMIT();
    int buf = 0;
    for (int kb = 0; kb < NKB; kb++) {
        CP_WAIT0();
        __syncthreads();
        if (kb + 1 < NKB) { loadKB(kb + 1, buf ^ 1); CP_COMMIT(); }
        uint32_t base = sB + buf * STG;
        #pragma unroll
        for (int km = 0; km < 2; km++) {
            uint32_t bh[NT][2], bl[NT][2];
            #pragma unroll
            for (int nt = 0; nt < NT; nt++) {
                uint32_t off = (uint32_t)(((wn * WN + nt * 8 + (lane & 7)) * 40
                               + km * 16 + ((lane >> 3) & 1) * 8) * 2);
                asm volatile("ldmatrix.sync.aligned.m8n8.x2.shared.b16 {%0,%1}, [%2];"
                             : "=r"(bh[nt][0]), "=r"(bh[nt][1]) : "r"(base + 2 * SZ_A + off));
                asm volatile("ldmatrix.sync.aligned.m8n8.x2.shared.b16 {%0,%1}, [%2];"
                             : "=r"(bl[nt][0]), "=r"(bl[nt][1]) : "r"(base + 2 * SZ_A + SZ_B + off));
            }
            #pragma unroll
            for (int mt = 0; mt < 4; mt++) {
                uint32_t ah[4], al[4];
                uint32_t off = (uint32_t)(((wm * 64 + mt * 16 + (lane & 15)) * 40
                               + km * 16 + (lane >> 4) * 8) * 2);
                asm volatile("ldmatrix.sync.aligned.m8n8.x4.shared.b16 {%0,%1,%2,%3}, [%4];"
                             : "=r"(ah[0]), "=r"(ah[1]), "=r"(ah[2]), "=r"(ah[3]) : "r"(base + off));
                asm volatile("ldmatrix.sync.aligned.m8n8.x4.shared.b16 {%0,%1,%2,%3}, [%4];"
                             : "=r"(al[0]), "=r"(al[1]), "=r"(al[2]), "=r"(al[3]) : "r"(base + SZ_A + off));
                #pragma unroll
                for (int nt = 0; nt < NT; nt++) {
                    MMA_BF16(acc[mt][nt], ah, bh[nt]);
                    MMA_BF16(acc[mt][nt], al, bh[nt]);
                    MMA_BF16(acc[mt][nt], ah, bl[nt]);
                }
            }
        }
        __syncthreads();
        buf ^= 1;
    }

    const int gr = lane >> 2, gc = (lane & 3) * 2;
    #pragma unroll
    for (int mt = 0; mt < 4; mt++) {
        unsigned row0 = mtBase + wm * 64 + mt * 16 + gr;
        unsigned row1 = row0 + 8;
        unsigned c0 = row0 & (W - 1), r0 = (row0 >> LW) & (W - 1), n0 = row0 >> (2 * LW);
        unsigned c1 = row1 & (W - 1), r1 = (row1 >> LW) & (W - 1), n1 = row1 >> (2 * LW);
        size_t base0 = ((size_t)(n0 * 2 * W + 2 * r0 + ph) * 2 * W + (2 * c0 + pw)) * NN;
        size_t base1 = ((size_t)(n1 * 2 * W + 2 * r1 + ph) * 2 * W + (2 * c1 + pw)) * NN;
        #pragma unroll
        for (int nt = 0; nt < NT; nt++) {
            int col = wn * WN + nt * 8 + gc;
            float b0 = bias[col], b1 = bias[col + 1];
            float v00 = fmaxf(acc[mt][nt][0] + b0, 0.f), v01 = fmaxf(acc[mt][nt][1] + b1, 0.f);
            float v10 = fmaxf(acc[mt][nt][2] + b0, 0.f), v11 = fmaxf(acc[mt][nt][3] + b1, 0.f);
            if (OUTSPLIT) {
                __nv_bfloat162 h0 = __floats2bfloat162_rn(v00, v01);
                __nv_bfloat162 h1 = __floats2bfloat162_rn(v10, v11);
                __nv_bfloat162 l0 = __floats2bfloat162_rn(v00 - __low2float(h0), v01 - __high2float(h0));
                __nv_bfloat162 l1 = __floats2bfloat162_rn(v10 - __low2float(h1), v11 - __high2float(h1));
                *reinterpret_cast<__nv_bfloat162*>(outH + base0 + col) = h0;
                *reinterpret_cast<__nv_bfloat162*>(outL + base0 + col) = l0;
                *reinterpret_cast<__nv_bfloat162*>(outH + base1 + col) = h1;
                *reinterpret_cast<__nv_bfloat162*>(outL + base1 + col) = l1;
            } else {
                *reinterpret_cast<float2*>(outF + base0 + col) = make_float2(v00, v01);
                *reinterpret_cast<float2*>(outF + base1 + col) = make_float2(v10, v11);
            }
        }
    }
}

// ---------------- scores HMMA with fused per-32-code group max ---------------
__global__ void __launch_bounds__(256, 2)
scores_hmma_k(const __nv_bfloat16* __restrict__ featb,
              const __nv_bfloat16* __restrict__ cbb,
              unsigned long long* __restrict__ grp)
{
    constexpr int LDS = 40;
    __shared__ __align__(16) __nv_bfloat16 As[2][128][LDS];
    __shared__ __align__(16) __nv_bfloat16 Bs[2][128][LDS];
    const int tid = threadIdx.x;
    const int lane = tid & 31, warp = tid >> 5;
    const int wm = warp >> 2, wn = warp & 3;
    const int mtBase = blockIdx.y * 128, ntBase = blockIdx.x * 128;
    const uint32_t aSm = smem_u32(As), bSm = smem_u32(Bs);

    float acc[4][4][4];
    #pragma unroll
    for (int i = 0; i < 4; i++)
        #pragma unroll
        for (int j = 0; j < 4; j++)
            #pragma unroll
            for (int rr = 0; rr < 4; rr++) acc[i][j][rr] = 0.f;

    auto loadTiles = [&](int kt, int buf) {
        int k0 = kt * 32;
        #pragma unroll
        for (int s = 0; s < 2; s++) {
            int idx = s * 256 + tid;
            int row = idx >> 2, c = idx & 3;
            const __nv_bfloat16* srcA = featb + (size_t)(mtBase + row) * 256 + k0 + c * 8;
            const __nv_bfloat16* srcB = cbb   + (size_t)(ntBase + row) * 256 + k0 + c * 8;
            uint32_t da = aSm + (uint32_t)(((buf * 128 + row) * LDS + c * 8) * 2);
            uint32_t db = bSm + (uint32_t)(((buf * 128 + row) * LDS + c * 8) * 2);
            CP_ASYNC16(da, srcA);
            CP_ASYNC16(db, srcB);
        }
    };

    loadTiles(0, 0);
    CP_COMMIT();

    int buf = 0;
    for (int kt = 0; kt < 8; kt++) {
        CP_WAIT0();
        __syncthreads();
        if (kt < 7) { loadTiles(kt + 1, buf ^ 1); CP_COMMIT(); }

        #pragma unroll
        for (int km = 0; km < 2; km++) {
            uint32_t a[4][4], b[4][2];
            #pragma unroll
            for (int mt = 0; mt < 4; mt++) {
                uint32_t addr = aSm + (uint32_t)((((buf * 128 + wm * 64 + mt * 16 + (lane & 15)) * LDS)
                                + km * 16 + ((lane >> 4) * 8)) * 2);
                asm volatile("ldmatrix.sync.aligned.m8n8.x4.shared.b16 {%0,%1,%2,%3}, [%4];"
                             : "=r"(a[mt][0]), "=r"(a[mt][1]), "=r"(a[mt][2]), "=r"(a[mt][3])
                             : "r"(addr));
            }
            #pragma unroll
            for (int nt = 0; nt < 4; nt++) {
                uint32_t addr = bSm + (uint32_t)((((buf * 128 + wn * 32 + nt * 8 + (lane & 7)) * LDS)
                                + km * 16 + (((lane >> 3) & 1) * 8)) * 2);
                asm volatile("ldmatrix.sync.aligned.m8n8.x2.shared.b16 {%0,%1}, [%2];"
                             : "=r"(b[nt][0]), "=r"(b[nt][1]) : "r"(addr));
            }
            #pragma unroll
            for (int mt = 0; mt < 4; mt++)
                #pragma unroll
                for (int nt = 0; nt < 4; nt++)
                    MMA_BF16(acc[mt][nt], a[mt], b[nt]);
        }
        __syncthreads();
        buf ^= 1;
    }

    const int g = blockIdx.x * 4 + wn;
    const int gc = (lane & 3) * 2;
    #pragma unroll
    for (int mt = 0; mt < 4; mt++) {
        unsigned long long k0 = 0ull, k1 = 0ull;
        #pragma unroll
        for (int nt = 0; nt < 4; nt++) {
            unsigned col = (unsigned)(ntBase + wn * 32 + nt * 8 + gc);
            unsigned long long t;
            t = mkkey(acc[mt][nt][0], col);     if (t > k0) k0 = t;
            t = mkkey(acc[mt][nt][1], col + 1); if (t > k0) k0 = t;
            t = mkkey(acc[mt][nt][2], col);     if (t > k1) k1 = t;
            t = mkkey(acc[mt][nt][3], col + 1); if (t > k1) k1 = t;
        }
        #pragma unroll
        for (int m = 1; m <= 2; m <<= 1) {
            unsigned long long o0 = __shfl_xor_sync(0xffffffffu, k0, m);
            unsigned long long o1 = __shfl_xor_sync(0xffffffffu, k1, m);
            if (o0 > k0) k0 = o0;
            if (o1 > k1) k1 = o1;
        }
        if ((lane & 3) == 0) {
            unsigned row0 = mtBase + wm * 64 + mt * 16 + (lane >> 2);
            grp[(size_t)row0 * 256 + g] = k0;
            grp[(size_t)(row0 + 8) * 256 + g] = k1;
        }
    }
}

// ---------------- rescue: exact fp32 argmax over candidate groups ------------
__global__ void __launch_bounds__(256)
rescue_k(const unsigned long long* __restrict__ grp, const float* __restrict__ feat,
         const float* __restrict__ cb,
         __nv_bfloat16* __restrict__ qh, __nv_bfloat16* __restrict__ ql,
         float* __restrict__ idx_out)
{
    __shared__ float fsh[256];
    __shared__ unsigned long long gk[256];
    __shared__ unsigned long long wmax[8];
    __shared__ float wsum[8];
    __shared__ unsigned long long bestk;
    __shared__ float thr_s;
    const int row = blockIdx.x, tid = threadIdx.x;
    const int lane = tid & 31, wid = tid >> 5;

    float fv = feat[(size_t)row * 256 + tid];
    fsh[tid] = fv;
    unsigned long long k = grp[(size_t)row * 256 + tid];
    gk[tid] = k;
    float ssq = fv * fv;
    #pragma unroll
    for (int m = 16; m; m >>= 1) {
        ssq += __shfl_xor_sync(0xffffffffu, ssq, m);
        unsigned long long o = __shfl_xor_sync(0xffffffffu, k, m);
        if (o > k) k = o;
    }
    if (lane == 0) { wsum[wid] = ssq; wmax[wid] = k; }
    __syncthreads();
    if (tid == 0) {
        float s = 0.f;
        unsigned long long g = 0ull;
        #pragma unroll
        for (int i = 0; i < 8; i++) { s += wsum[i]; if (wmax[i] > g) g = wmax[i]; }
        thr_s = iford((unsigned)(g >> 32)) - 0.1f * sqrtf(s);
        bestk = 0ull;
    }
    __syncthreads();

    unsigned long long lb = 0ull;
    for (int g = wid; g < 256; g += 8) {
        if (iford((unsigned)(gk[g] >> 32)) < thr_s) continue;
        #pragma unroll 1
        for (int cc = 0; cc < 32; cc++) {
            unsigned code = (unsigned)(g * 32 + cc);
            const float4* crow = reinterpret_cast<const float4*>(cb + (size_t)code * 256);
            const float4* frow = reinterpret_cast<const float4*>(fsh);
            float a = 0.f;
            #pragma unroll
            for (int j = 0; j < 2; j++) {
                float4 cv = crow[lane * 2 + j];
                float4 fq = frow[lane * 2 + j];
                a += fq.x * cv.x + fq.y * cv.y + fq.z * cv.z + fq.w * cv.w;
            }
            #pragma unroll
            for (int m = 16; m; m >>= 1) a += __shfl_xor_sync(0xffffffffu, a, m);
            if (lane == 0) {
                unsigned long long kk = mkkey(a, code);
                if (kk > lb) lb = kk;
            }
        }
    }
    if (lane == 0 && lb) atomicMax(&bestk, lb);
    __syncthreads();

    unsigned code = 0xFFFFFFFFu - (unsigned)(bestk & 0xFFFFFFFFull);
    float v = cb[(size_t)code * 256 + tid];
    __nv_bfloat16 h = __float2bfloat16(v);
    qh[(size_t)row * 256 + tid] = h;
    ql[(size_t)row * 256 + tid] = __float2bfloat16(v - __bfloat162float(h));
    if (tid == 0 && idx_out) idx_out[row] = (float)code;
}

// ---------------- deconv3: direct, Cout=3, NHWC in -> NCHW out --------------
__global__ void deconv3_k(const float* __restrict__ in, const float* __restrict__ w,
                          const float* __restrict__ b, float* __restrict__ out)
{
    __shared__ float ws[3 * 64 * 16];
    for (int i = threadIdx.x; i < 3072; i += THREADS) ws[i] = w[i];
    __syncthreads();
    int gid = blockIdx.x * THREADS + threadIdx.x;
    int ow = gid & 255;
    int oh = (gid >> 8) & 255;
    int n  = gid >> 16;
    int ph = oh & 1, pw = ow & 1;
    int r = oh >> 1, c = ow >> 1;
    float a0 = b[0], a1 = b[1], a2 = b[2];
    #pragma unroll
    for (int th = 0; th < 2; th++) {
        int ih = r + th - 1 + ph;
        if ((unsigned)ih >= 128u) continue;
        int kh = 2 * th + ph;
        #pragma unroll
        for (int tw = 0; tw < 2; tw++) {
            int iw = c + tw - 1 + pw;
            if ((unsigned)iw >= 128u) continue;
            int kw = 2 * tw + pw;
            const float* xp = in + ((size_t)(n * 128 + ih) * 128 + iw) * 64;
            int wo = kh * 4 + kw;
            #pragma unroll
            for (int c4 = 0; c4 < 16; c4++) {
                float4 xv = *reinterpret_cast<const float4*>(xp + c4 * 4);
                int ci = c4 * 4;
                a0 += xv.x * ws[(0 * 64 + ci) * 16 + wo] + xv.y * ws[(0 * 64 + ci + 1) * 16 + wo]
                    + xv.z * ws[(0 * 64 + ci + 2) * 16 + wo] + xv.w * ws[(0 * 64 + ci + 3) * 16 + wo];
                a1 += xv.x * ws[(1 * 64 + ci) * 16 + wo] + xv.y * ws[(1 * 64 + ci + 1) * 16 + wo]
                    + xv.z * ws[(1 * 64 + ci + 2) * 16 + wo] + xv.w * ws[(1 * 64 + ci + 3) * 16 + wo];
                a2 += xv.x * ws[(2 * 64 + ci) * 16 + wo] + xv.y * ws[(2 * 64 + ci + 1) * 16 + wo]
                    + xv.z * ws[(2 * 64 + ci + 2) * 16 + wo] + xv.w * ws[(2 * 64 + ci + 3) * 16 + wo];
            }
        }
    }
    size_t p = (size_t)n * 3 * 65536 + (size_t)oh * 256 + ow;
    out[p] = a0;
    out[p + 65536] = a1;
    out[p + 2 * 65536] = a2;
}

// ---------------------------------------------------------------------------
extern "C" void kernel_launch(void* const* d_in, const int* in_sizes, int n_in,
                              void* d_out, int out_size)
{
    const float* x   = (const float*)d_in[0];
    const float* ew1 = (const float*)d_in[1];
    const float* eb1 = (const float*)d_in[2];
    const float* ew2 = (const float*)d_in[3];
    const float* eb2 = (const float*)d_in[4];
    const float* ew3 = (const float*)d_in[5];
    const float* eb3 = (const float*)d_in[6];
    const float* cb  = (const float*)d_in[7];
    const float* dw1 = (const float*)d_in[8];
    const float* db1 = (const float*)d_in[9];
    const float* dw2 = (const float*)d_in[10];
    const float* db2 = (const float*)d_in[11];
    const float* dw3 = (const float*)d_in[12];
    const float* db3 = (const float*)d_in[13];
    float* out = (float*)d_out;

    float *h1, *h2, *feat, *d2, *wp;
    __nv_bfloat16 *cbb, *fb, *qh, *ql, *xh, *xl;
    unsigned long long* grp;
    cudaGetSymbolAddress((void**)&h1,   g_h1);
    cudaGetSymbolAddress((void**)&h2,   g_h2);
    cudaGetSymbolAddress((void**)&feat, g_feat);
    cudaGetSymbolAddress((void**)&d2,   g_d2);
    cudaGetSymbolAddress((void**)&wp,   g_wp);
    cudaGetSymbolAddress((void**)&cbb,  g_cbb);
    cudaGetSymbolAddress((void**)&fb,   g_fb);
    cudaGetSymbolAddress((void**)&grp,  g_grp);
    cudaGetSymbolAddress((void**)&qh,   g_qh);
    cudaGetSymbolAddress((void**)&ql,   g_ql);
    cudaGetSymbolAddress((void**)&xh,   g_xh);
    cudaGetSymbolAddress((void**)&xl,   g_xl);

    float* wp3 = wp;                                           // 524288 f
    float* wp2 = wp + 524288;                                  // 131072 f
    __nv_bfloat16* wh1 = (__nv_bfloat16*)(wp + 655360);        // 524288 bf
    __nv_bfloat16* wl1 = (__nv_bfloat16*)(wp + 917504);        // 524288 bf
    __nv_bfloat16* wh2 = (__nv_bfloat16*)(wp + 1179648);       // 131072 bf
    __nv_bfloat16* wl2 = (__nv_bfloat16*)(wp + 1245184);       // 131072 bf

    const int RECON = 16 * 3 * 256 * 256;
    float* idx_out = (out_size >= RECON + 16384) ? (out + RECON) : nullptr;

    // 1: conv1 (conflict-free smem weights) + ALL prep
    conv1_prep_k<<<65536 + 512 + 2048 + 2048 + 2048 + 512, THREADS>>>(
        x, ew1, eb1, h1, ew2, wp2, ew3, wp3, cb, cbb, dw1, wh1, wl1, dw2, wh2, wl2);

    // 2-3: encoder GEMMs (fp32 exact)
    gemm_k<6, 6, 0><<<dim3(1, 512), THREADS>>>(h1, wp2, 65536, 128, 1024, eb2, h2, nullptr);
    gemm_k<7, 5, 2><<<dim3(2, 128), THREADS>>>(h2, wp3, 16384, 256, 2048, eb3, feat, fb);

    // 4-5: quantize
    scores_hmma_k<<<dim3(64, 128), THREADS>>>(fb, cbb, grp);
    rescue_k<<<16384, THREADS>>>(grp, feat, cb, qh, ql, idx_out);

    // 6-7: decoder split-bf16 HMMA deconvs (128-row tiles)
    {
        constexpr int SMEM1 = 2 * (2 * 128 * 40 * 2 + 2 * 128 * 40 * 2);   // 81920
        cudaFuncSetAttribute((const void*)deconv_hmma_k<8, 5, 128, 32, true>,
                             cudaFuncAttributeMaxDynamicSharedMemorySize, SMEM1);
        deconv_hmma_k<8, 5, 128, 32, true><<<dim3(128, 1, 4), THREADS, SMEM1>>>(
            qh, ql, wh1, wl1, db1, nullptr, xh, xl);
    }
    {
        constexpr int SMEM2 = 2 * (2 * 128 * 40 * 2 + 2 * 64 * 40 * 2);    // 61440
        cudaFuncSetAttribute((const void*)deconv_hmma_k<7, 6, 64, 16, false>,
                             cudaFuncAttributeMaxDynamicSharedMemorySize, SMEM2);
        deconv_hmma_k<7, 6, 64, 16, false><<<dim3(512, 1, 4), THREADS, SMEM2>>>(
            xh, xl, wh2, wl2, db2, d2, nullptr, nullptr);
    }

    // 8: final deconv
    deconv3_k<<<4096, THREADS>>>(d2, dw3, db3, out);
}

// round 12
// speedup vs baseline: 1.6948x; 1.1670x over previous
#include <cuda_runtime.h>
#include <cuda_bf16.h>
#include <math.h>
#include <stdint.h>

#define THREADS 256

// ---------------- scratch (device globals; no allocation allowed) ----------
__device__ float g_h1  [16u*128u*128u*64u];             // conv1 out NHWC (67MB)
__device__ float g_h2  [65536u*128u];                   // conv2 out NHWC
__device__ float g_feat[16384u*256u];                   // conv3 out (fp32 exact)
__device__ float g_d2  [16u*128u*128u*64u];             // deconv2 out NHWC fp32
__device__ float g_wp  [2097152u];                      // packed weights (8MB)
__device__ __nv_bfloat16 g_cbb[8192u*256u];             // codebook bf16
__device__ __nv_bfloat16 g_fb[16384u*256u];             // feat bf16
__device__ unsigned long long g_grp[16384u*256u];       // per-32-code group max keys
__device__ __nv_bfloat16 g_qh[16384u*256u];             // quantized hi
__device__ __nv_bfloat16 g_ql[16384u*256u];             // quantized lo
__device__ __nv_bfloat16 g_xh[16u*64u*64u*128u];        // deconv1 out hi
__device__ __nv_bfloat16 g_xl[16u*64u*64u*128u];        // deconv1 out lo

// ---------------- helpers ----------------------------------------------------
__device__ __forceinline__ uint32_t smem_u32(const void* p) {
    uint32_t a;
    asm("{ .reg .u64 t; cvta.to.shared.u64 t, %1; cvt.u32.u64 %0, t; }" : "=r"(a) : "l"(p));
    return a;
}
#define CP_ASYNC16(dst, src) \
    asm volatile("cp.async.cg.shared.global [%0], [%1], 16;" :: "r"(dst), "l"(src) : "memory")
#define CP_ASYNC16Z(dst, src, n) \
    asm volatile("cp.async.cg.shared.global [%0], [%1], 16, %2;" :: "r"(dst), "l"(src), "r"(n) : "memory")
#define CP_COMMIT() asm volatile("cp.async.commit_group;" ::: "memory")
#define CP_WAIT0()  asm volatile("cp.async.wait_group 0;" ::: "memory")

__device__ __forceinline__ unsigned ford(float f) {
    unsigned u = __float_as_uint(f);
    return (u & 0x80000000u) ? ~u : (u | 0x80000000u);
}
__device__ __forceinline__ float iford(unsigned e) {
    return (e & 0x80000000u) ? __uint_as_float(e ^ 0x80000000u) : __uint_as_float(~e);
}
__device__ __forceinline__ unsigned long long mkkey(float v, unsigned idx) {
    return ((unsigned long long)ford(v) << 32) | (0xFFFFFFFFu - idx);
}

#define MMA_BF16(ACC, A, B) \
    asm volatile("mma.sync.aligned.m16n8k16.row.col.f32.bf16.bf16.f32 " \
        "{%0,%1,%2,%3}, {%4,%5,%6,%7}, {%8,%9}, {%0,%1,%2,%3};" \
        : "+f"((ACC)[0]), "+f"((ACC)[1]), "+f"((ACC)[2]), "+f"((ACC)[3]) \
        : "r"((A)[0]), "r"((A)[1]), "r"((A)[2]), "r"((A)[3]), "r"((B)[0]), "r"((B)[1]))
#define LDMX4(R, A) \
    asm volatile("ldmatrix.sync.aligned.m8n8.x4.shared.b16 {%0,%1,%2,%3}, [%4];" \
        : "=r"((R)[0]), "=r"((R)[1]), "=r"((R)[2]), "=r"((R)[3]) : "r"(A))
#define LDMX2(R, A) \
    asm volatile("ldmatrix.sync.aligned.m8n8.x2.shared.b16 {%0,%1}, [%2];" \
        : "=r"((R)[0]), "=r"((R)[1]) : "r"(A))

// ---------------- prep device functions --------------------------------------
__device__ __forceinline__ void pack_w_conv_b(const float* __restrict__ w,
                                              float* __restrict__ Bp,
                                              int Ci, int Co, int gid)
{
    int k = gid / Co, co = gid % Co;
    int ci = k % Ci;
    int kidx = k / Ci;
    int kh = kidx >> 2, kw = kidx & 3;
    Bp[gid] = w[(((size_t)co * Ci + ci) * 4 + kh) * 4 + kw];
}

__device__ __forceinline__ void pack_w_deconv_b(const float* __restrict__ w,
                                                __nv_bfloat16* __restrict__ Bh,
                                                __nv_bfloat16* __restrict__ Bl,
                                                int Ci, int Co, int gid)
{
    int K = 4 * Ci;
    int cls = gid / (K * Co);
    int g2 = gid % (K * Co);
    int n = g2 / K, k = g2 % K;
    int ci = k % Ci;
    int kidx = k / Ci;
    int th = kidx >> 1, tw = kidx & 1;
    int kh = 2 * th + (cls >> 1);
    int kw = 2 * tw + (cls & 1);
    float v = w[(((size_t)n * Ci + ci) * 4 + kh) * 4 + kw];
    __nv_bfloat16 h = __float2bfloat16(v);
    Bh[gid] = h;
    Bl[gid] = __float2bfloat16(v - __bfloat162float(h));
}

// ---------------- conv1 (4 co/thread, fp32 out, bit-exact) + all prep --------
__global__ void conv1_prep_k(const float* __restrict__ x, const float* __restrict__ w,
                             const float* __restrict__ b, float* __restrict__ y,
                             const float* __restrict__ ew2, float* __restrict__ wp2,
                             const float* __restrict__ ew3, float* __restrict__ wp3,
                             const float* __restrict__ cb, __nv_bfloat16* __restrict__ cbb,
                             const float* __restrict__ dw1, __nv_bfloat16* __restrict__ wh1,
                             __nv_bfloat16* __restrict__ wl1,
                             const float* __restrict__ dw2, __nv_bfloat16* __restrict__ wh2,
                             __nv_bfloat16* __restrict__ wl2)
{
    const int bid = blockIdx.x;
    const int tid = threadIdx.x;
    if (bid < 16384) {
        __shared__ float4 ws4[48 * 16];        // [idx][co4] -> broadcast-friendly
        for (int j = tid; j < 768; j += THREADS) {
            int idx = j >> 4, c4 = j & 15;
            ws4[j] = make_float4(w[(c4 * 4 + 0) * 48 + idx], w[(c4 * 4 + 1) * 48 + idx],
                                 w[(c4 * 4 + 2) * 48 + idx], w[(c4 * 4 + 3) * 48 + idx]);
        }
        __syncthreads();
        unsigned gid = bid * THREADS + tid;    // [n, oh, ow, co4]
        int co4 = gid & 15;
        int ow = (gid >> 4) & 127;
        int oh = (gid >> 11) & 127;
        int n  = gid >> 18;
        float a0 = b[co4 * 4], a1 = b[co4 * 4 + 1], a2 = b[co4 * 4 + 2], a3 = b[co4 * 4 + 3];
        #pragma unroll
        for (int kh = 0; kh < 4; kh++) {
            int ih = 2 * oh + kh - 1;
            if ((unsigned)ih >= 256u) continue;
            #pragma unroll
            for (int kw = 0; kw < 4; kw++) {
                int iw = 2 * ow + kw - 1;
                if ((unsigned)iw >= 256u) continue;
                #pragma unroll
                for (int ci = 0; ci < 3; ci++) {
                    float px = x[((size_t)(n * 3 + ci) * 256 + ih) * 256 + iw];
                    float4 wv = ws4[(ci * 16 + kh * 4 + kw) * 16 + co4];
                    a0 += px * wv.x; a1 += px * wv.y; a2 += px * wv.z; a3 += px * wv.w;
                }
            }
        }
        float4 o = make_float4(fmaxf(a0, 0.f), fmaxf(a1, 0.f), fmaxf(a2, 0.f), fmaxf(a3, 0.f));
        *reinterpret_cast<float4*>(y + (size_t)gid * 4) = o;
    } else if (bid < 16384 + 512) {
        int gid = (bid - 16384) * THREADS + tid;
        pack_w_conv_b(ew2, wp2, 64, 128, gid);
    } else if (bid < 16384 + 512 + 2048) {
        int gid = (bid - (16384 + 512)) * THREADS + tid;
        pack_w_conv_b(ew3, wp3, 128, 256, gid);
    } else if (bid < 16384 + 512 + 2048 + 2048) {
        unsigned i = (bid - (16384 + 512 + 2048)) * THREADS + tid;
        float4 v = reinterpret_cast<const float4*>(cb)[i];
        __nv_bfloat162* o = reinterpret_cast<__nv_bfloat162*>(cbb) + 2u * i;
        o[0] = __nv_bfloat162(__float2bfloat16(v.x), __float2bfloat16(v.y));
        o[1] = __nv_bfloat162(__float2bfloat16(v.z), __float2bfloat16(v.w));
    } else if (bid < 16384 + 512 + 2048 + 2048 + 2048) {
        int gid = (bid - (16384 + 512 + 2048 + 2048)) * THREADS + tid;
        pack_w_deconv_b(dw1, wh1, wl1, 256, 128, gid);
    } else {
        int gid = (bid - (16384 + 512 + 2048 + 2048 + 2048)) * THREADS + tid;
        pack_w_deconv_b(dw2, wh2, wl2, 128, 64, gid);
    }
}

// ---------------- implicit-im2col SGEMM (fp32, encoder) ----------------------
// MODE 0: out = relu(acc+bias); MODE 2: out fp32 + out2 bf16 (no relu)
template<int LC, int LW, int MODE>
__global__ void __launch_bounds__(256, 2)
gemm_k(const float* __restrict__ Asrc, const float* __restrict__ B,
       int M, int N, int K,
       const float* __restrict__ bias,
       float* __restrict__ out, __nv_bfloat16* __restrict__ out2)
{
    constexpr int BM = 128, BK = 16, BN = 128, TM = 8, TN = 8;
    constexpr unsigned C = 1u << LC;
    constexpr unsigned W = 1u << LW;
    __shared__ float As[BK][BM];
    __shared__ float Bs[BK][BN];
    int tid = threadIdx.x;
    int tx = tid & 15, ty = tid >> 4;
    int rowBase = blockIdx.y * BM;
    int colBase = blockIdx.x * BN;

    const int r = tid >> 1;
    const unsigned row = rowBase + r;
    const unsigned cw = row & (W - 1);
    const unsigned rh = (row >> LW) & (W - 1);
    const unsigned n  = row >> (2 * LW);

    float acc[TM][TN];
    #pragma unroll
    for (int j = 0; j < TM; j++)
        #pragma unroll
        for (int i = 0; i < TN; i++) acc[j][i] = 0.f;

    for (int k0 = 0; k0 < K; k0 += BK) {
        #pragma unroll
        for (int t = 0; t < 2; ++t) {
            int kq = (tid & 1) * 2 + t;
            int k = k0 + kq * 4;
            unsigned ci = (unsigned)k & (C - 1);
            int kidx = k >> LC;
            int kh = kidx >> 2, kw = kidx & 3;
            int ih = 2 * (int)rh + kh - 1, iw = 2 * (int)cw + kw - 1;
            float4 v = make_float4(0.f, 0.f, 0.f, 0.f);
            if ((unsigned)ih < 2 * W && (unsigned)iw < 2 * W)
                v = *reinterpret_cast<const float4*>(
                    Asrc + ((((size_t)n * 2 * W + ih) * 2 * W + iw) << LC) + ci);
            As[kq * 4 + 0][r] = v.x;
            As[kq * 4 + 1][r] = v.y;
            As[kq * 4 + 2][r] = v.z;
            As[kq * 4 + 3][r] = v.w;
        }
        #pragma unroll
        for (int t = 0; t < 2; ++t) {
            int idx = t * 256 + tid;
            int kk = idx >> 5;
            int c4 = idx & 31;
            float4 v = *reinterpret_cast<const float4*>(B + (size_t)(k0 + kk) * N + colBase + c4 * 4);
            *reinterpret_cast<float4*>(&Bs[kk][c4 * 4]) = v;
        }
        __syncthreads();
        #pragma unroll
        for (int k = 0; k < BK; ++k) {
            float4 a0 = *reinterpret_cast<const float4*>(&As[k][ty * TM]);
            float4 a1 = *reinterpret_cast<const float4*>(&As[k][ty * TM + 4]);
            float a[TM] = {a0.x, a0.y, a0.z, a0.w, a1.x, a1.y, a1.z, a1.w};
            float b[TN];
            #pragma unroll
            for (int qq = 0; qq < 2; qq++) {
                float4 bv = *reinterpret_cast<const float4*>(&Bs[k][tx * TN + qq * 4]);
                b[qq * 4 + 0] = bv.x; b[qq * 4 + 1] = bv.y; b[qq * 4 + 2] = bv.z; b[qq * 4 + 3] = bv.w;
            }
            #pragma unroll
            for (int j = 0; j < TM; j++)
                #pragma unroll
                for (int i = 0; i < TN; i++)
                    acc[j][i] += a[j] * b[i];
        }
        __syncthreads();
    }

    #pragma unroll
    for (int j = 0; j < TM; j++) {
        int orow = rowBase + ty * TM + j;
        #pragma unroll
        for (int i = 0; i < TN; i++) {
            int col = colBase + tx * TN + i;
            float v = acc[j][i] + bias[col];
            if (MODE == 0) v = fmaxf(v, 0.f);
            out[(size_t)orow * N + col] = v;
            if (MODE == 2) out2[(size_t)orow * N + col] = __float2bfloat16(v);
        }
    }
}

// ---------------- deconv via split-bf16 HMMA, double-buffered (128-row) ------
template<int LC, int LW, int NN, int WN, bool OUTSPLIT>
__global__ void __launch_bounds__(256, 2)
deconv_hmma_k(const __nv_bfloat16* __restrict__ Ahg, const __nv_bfloat16* __restrict__ Alg,
              const __nv_bfloat16* __restrict__ Bhg, const __nv_bfloat16* __restrict__ Blg,
              const float* __restrict__ bias,
              float* __restrict__ outF,
              __nv_bfloat16* __restrict__ outH, __nv_bfloat16* __restrict__ outL)
{
    constexpr int K = 4 << LC;
    constexpr int NKB = K / 32;
    constexpr unsigned C = 1u << LC, W = 1u << LW;
    constexpr int NT = WN / 8;
    constexpr int SZ_A = 128 * 40 * 2;
    constexpr int SZ_B = NN * 40 * 2;
    constexpr int STG = 2 * SZ_A + 2 * SZ_B;
    extern __shared__ __align__(16) char dsm[];
    const uint32_t sB = smem_u32(dsm);
    const int tid = threadIdx.x, lane = tid & 31, warp = tid >> 5;
    const int wm = warp >> 2, wn = warp & 3;
    const int mtBase = blockIdx.x * 128;
    const int z = blockIdx.z;
    const int ph = z >> 1, pw = z & 1;
    const __nv_bfloat16* BhC = Bhg + (size_t)z * NN * K;
    const __nv_bfloat16* BlC = Blg + (size_t)z * NN * K;

    float acc[4][NT][4];
    #pragma unroll
    for (int i = 0; i < 4; i++)
        #pragma unroll
        for (int j = 0; j < NT; j++)
            #pragma unroll
            for (int rr = 0; rr < 4; rr++) acc[i][j][rr] = 0.f;

    auto loadKB = [&](int kb, int buf) {
        int k0 = kb * 32;
        int kidx = k0 >> LC;
        int th = kidx >> 1, tw = kidx & 1;
        unsigned cib = (unsigned)k0 & (C - 1);
        uint32_t base = sB + buf * STG;
        #pragma unroll
        for (int s = 0; s < 4; s++) {
            int t = s * 256 + tid;
            int rl = t >> 3, c4 = t & 3, hl = (t >> 2) & 1;
            unsigned grow = mtBase + rl;
            unsigned cc = grow & (W - 1), rr2 = (grow >> LW) & (W - 1), nn2 = grow >> (2 * LW);
            int ih = (int)rr2 + th - 1 + ph, iw = (int)cc + tw - 1 + pw;
            int inb = ((unsigned)ih < W && (unsigned)iw < W) ? 16 : 0;
            size_t so = ((((size_t)nn2 * W + (unsigned)ih) * W + (unsigned)iw) << LC) + cib + c4 * 8;
            const __nv_bfloat16* src = (hl ? Alg : Ahg) + (inb ? so : 0);
            uint32_t dst = base + (hl ? SZ_A : 0) + (uint32_t)(rl * 80 + c4 * 16);
            CP_ASYNC16Z(dst, src, inb);
        }
        #pragma unroll
        for (int s = 0; s < NN / 32; s++) {
            int t = s * 256 + tid;
            int nl = t >> 3, c4 = t & 3, hl = (t >> 2) & 1;
            const __nv_bfloat16* src = (hl ? BlC : BhC) + (size_t)nl * K + k0 + c4 * 8;
            uint32_t dst = base + 2 * SZ_A + (hl ? SZ_B : 0) + (uint32_t)(nl * 80 + c4 * 16);
            CP_ASYNC16(dst, src);
        }
    };

    loadKB(0, 0);
    CP_COMMIT();
    int buf = 0;
    for (int kb = 0; kb < NKB; kb++) {
        CP_WAIT0();
        __syncthreads();
        if (kb + 1 < NKB) { loadKB(kb + 1, buf ^ 1); CP_COMMIT(); }
        uint32_t base = sB + buf * STG;
        #pragma unroll
        for (int km = 0; km < 2; km++) {
            uint32_t bh[NT][2], bl[NT][2];
            #pragma unroll
            for (int nt = 0; nt < NT; nt++) {
                uint32_t off = (uint32_t)(((wn * WN + nt * 8 + (lane & 7)) * 40
                               + km * 16 + ((lane >> 3) & 1) * 8) * 2);
                LDMX2(bh[nt], base + 2 * SZ_A + off);
                LDMX2(bl[nt], base + 2 * SZ_A + SZ_B + off);
            }
            #pragma unroll
            for (int mt = 0; mt < 4; mt++) {
                uint32_t ah[4], al[4];
                uint32_t off = (uint32_t)(((wm * 64 + mt * 16 + (lane & 15)) * 40
                               + km * 16 + (lane >> 4) * 8) * 2);
                LDMX4(ah, base + off);
                LDMX4(al, base + SZ_A + off);
                #pragma unroll
                for (int nt = 0; nt < NT; nt++) {
                    MMA_BF16(acc[mt][nt], ah, bh[nt]);
                    MMA_BF16(acc[mt][nt], al, bh[nt]);
                    MMA_BF16(acc[mt][nt], ah, bl[nt]);
                }
            }
        }
        __syncthreads();
        buf ^= 1;
    }

    const int gr = lane >> 2, gc = (lane & 3) * 2;
    #pragma unroll
    for (int mt = 0; mt < 4; mt++) {
        unsigned row0 = mtBase + wm * 64 + mt * 16 + gr;
        unsigned row1 = row0 + 8;
        unsigned c0 = row0 & (W - 1), r0 = (row0 >> LW) & (W - 1), n0 = row0 >> (2 * LW);
        unsigned c1 = row1 & (W - 1), r1 = (row1 >> LW) & (W - 1), n1 = row1 >> (2 * LW);
        size_t base0 = ((size_t)(n0 * 2 * W + 2 * r0 + ph) * 2 * W + (2 * c0 + pw)) * NN;
        size_t base1 = ((size_t)(n1 * 2 * W + 2 * r1 + ph) * 2 * W + (2 * c1 + pw)) * NN;
        #pragma unroll
        for (int nt = 0; nt < NT; nt++) {
            int col = wn * WN + nt * 8 + gc;
            float b0 = bias[col], b1 = bias[col + 1];
            float v00 = fmaxf(acc[mt][nt][0] + b0, 0.f), v01 = fmaxf(acc[mt][nt][1] + b1, 0.f);
            float v10 = fmaxf(acc[mt][nt][2] + b0, 0.f), v11 = fmaxf(acc[mt][nt][3] + b1, 0.f);
            if (OUTSPLIT) {
                __nv_bfloat162 h0 = __floats2bfloat162_rn(v00, v01);
                __nv_bfloat162 h1 = __floats2bfloat162_rn(v10, v11);
                __nv_bfloat162 l0 = __floats2bfloat162_rn(v00 - __low2float(h0), v01 - __high2float(h0));
                __nv_bfloat162 l1 = __floats2bfloat162_rn(v10 - __low2float(h1), v11 - __high2float(h1));
                *reinterpret_cast<__nv_bfloat162*>(outH + base0 + col) = h0;
                *reinterpret_cast<__nv_bfloat162*>(outL + base0 + col) = l0;
                *reinterpret_cast<__nv_bfloat162*>(outH + base1 + col) = h1;
                *reinterpret_cast<__nv_bfloat162*>(outL + base1 + col) = l1;
            } else {
                *reinterpret_cast<float2*>(outF + base0 + col) = make_float2(v00, v01);
                *reinterpret_cast<float2*>(outF + base1 + col) = make_float2(v10, v11);
            }
        }
    }
}

// ---------------- scores HMMA with fused per-32-code group max ---------------
__global__ void __launch_bounds__(256, 2)
scores_hmma_k(const __nv_bfloat16* __restrict__ featb,
              const __nv_bfloat16* __restrict__ cbb,
              unsigned long long* __restrict__ grp)
{
    constexpr int LDS = 40;
    __shared__ __align__(16) __nv_bfloat16 As[2][128][LDS];
    __shared__ __align__(16) __nv_bfloat16 Bs[2][128][LDS];
    const int tid = threadIdx.x;
    const int lane = tid & 31, warp = tid >> 5;
    const int wm = warp >> 2, wn = warp & 3;
    const int mtBase = blockIdx.y * 128, ntBase = blockIdx.x * 128;
    const uint32_t aSm = smem_u32(As), bSm = smem_u32(Bs);

    float acc[4][4][4];
    #pragma unroll
    for (int i = 0; i < 4; i++)
        #pragma unroll
        for (int j = 0; j < 4; j++)
            #pragma unroll
            for (int rr = 0; rr < 4; rr++) acc[i][j][rr] = 0.f;

    auto loadTiles = [&](int kt, int buf) {
        int k0 = kt * 32;
        #pragma unroll
        for (int s = 0; s < 2; s++) {
            int idx = s * 256 + tid;
            int row = idx >> 2, c = idx & 3;
            const __nv_bfloat16* srcA = featb + (size_t)(mtBase + row) * 256 + k0 + c * 8;
            const __nv_bfloat16* srcB = cbb   + (size_t)(ntBase + row) * 256 + k0 + c * 8;
            uint32_t da = aSm + (uint32_t)(((buf * 128 + row) * LDS + c * 8) * 2);
            uint32_t db = bSm + (uint32_t)(((buf * 128 + row) * LDS + c * 8) * 2);
            CP_ASYNC16(da, srcA);
            CP_ASYNC16(db, srcB);
        }
    };

    loadTiles(0, 0);
    CP_COMMIT();

    int buf = 0;
    for (int kt = 0; kt < 8; kt++) {
        CP_WAIT0();
        __syncthreads();
        if (kt < 7) { loadTiles(kt + 1, buf ^ 1); CP_COMMIT(); }

        #pragma unroll
        for (int km = 0; km < 2; km++) {
            uint32_t a[4][4], b[4][2];
            #pragma unroll
            for (int mt = 0; mt < 4; mt++) {
                uint32_t addr = aSm + (uint32_t)((((buf * 128 + wm * 64 + mt * 16 + (lane & 15)) * LDS)
                                + km * 16 + ((lane >> 4) * 8)) * 2);
                LDMX4(a[mt], addr);
            }
            #pragma unroll
            for (int nt = 0; nt < 4; nt++) {
                uint32_t addr = bSm + (uint32_t)((((buf * 128 + wn * 32 + nt * 8 + (lane & 7)) * LDS)
                                + km * 16 + (((lane >> 3) & 1) * 8)) * 2);
                LDMX2(b[nt], addr);
            }
            #pragma unroll
            for (int mt = 0; mt < 4; mt++)
                #pragma unroll
                for (int nt = 0; nt < 4; nt++)
                    MMA_BF16(acc[mt][nt], a[mt], b[nt]);
        }
        __syncthreads();
        buf ^= 1;
    }

    const int g = blockIdx.x * 4 + wn;
    const int gc = (lane & 3) * 2;
    #pragma unroll
    for (int mt = 0; mt < 4; mt++) {
        unsigned long long k0 = 0ull, k1 = 0ull;
        #pragma unroll
        for (int nt = 0; nt < 4; nt++) {
            unsigned col = (unsigned)(ntBase + wn * 32 + nt * 8 + gc);
            unsigned long long t;
            t = mkkey(acc[mt][nt][0], col);     if (t > k0) k0 = t;
            t = mkkey(acc[mt][nt][1], col + 1); if (t > k0) k0 = t;
            t = mkkey(acc[mt][nt][2], col);     if (t > k1) k1 = t;
            t = mkkey(acc[mt][nt][3], col + 1); if (t > k1) k1 = t;
        }
        #pragma unroll
        for (int m = 1; m <= 2; m <<= 1) {
            unsigned long long o0 = __shfl_xor_sync(0xffffffffu, k0, m);
            unsigned long long o1 = __shfl_xor_sync(0xffffffffu, k1, m);
            if (o0 > k0) k0 = o0;
            if (o1 > k1) k1 = o1;
        }
        if ((lane & 3) == 0) {
            unsigned row0 = mtBase + wm * 64 + mt * 16 + (lane >> 2);
            grp[(size_t)row0 * 256 + g] = k0;
            grp[(size_t)(row0 + 8) * 256 + g] = k1;
        }
    }
}

// ---------------- rescue: exact fp32 argmax over candidate groups ------------
__global__ void __launch_bounds__(256)
rescue_k(const unsigned long long* __restrict__ grp, const float* __restrict__ feat,
         const float* __restrict__ cb,
         __nv_bfloat16* __restrict__ qh, __nv_bfloat16* __restrict__ ql,
         float* __restrict__ idx_out)
{
    __shared__ float fsh[256];
    __shared__ unsigned long long gk[256];
    __shared__ unsigned long long wmax[8];
    __shared__ float wsum[8];
    __shared__ unsigned long long bestk;
    __shared__ float thr_s;
    const int row = blockIdx.x, tid = threadIdx.x;
    const int lane = tid & 31, wid = tid >> 5;

    float fv = feat[(size_t)row * 256 + tid];
    fsh[tid] = fv;
    unsigned long long k = grp[(size_t)row * 256 + tid];
    gk[tid] = k;
    float ssq = fv * fv;
    #pragma unroll
    for (int m = 16; m; m >>= 1) {
        ssq += __shfl_xor_sync(0xffffffffu, ssq, m);
        unsigned long long o = __shfl_xor_sync(0xffffffffu, k, m);
        if (o > k) k = o;
    }
    if (lane == 0) { wsum[wid] = ssq; wmax[wid] = k; }
    __syncthreads();
    if (tid == 0) {
        float s = 0.f;
        unsigned long long g = 0ull;
        #pragma unroll
        for (int i = 0; i < 8; i++) { s += wsum[i]; if (wmax[i] > g) g = wmax[i]; }
        thr_s = iford((unsigned)(g >> 32)) - 0.1f * sqrtf(s);
        bestk = 0ull;
    }
    __syncthreads();

    unsigned long long lb = 0ull;
    for (int g = wid; g < 256; g += 8) {
        if (iford((unsigned)(gk[g] >> 32)) < thr_s) continue;
        #pragma unroll 1
        for (int cc = 0; cc < 32; cc++) {
            unsigned code = (unsigned)(g * 32 + cc);
            const float4* crow = reinterpret_cast<const float4*>(cb + (size_t)code * 256);
            const float4* frow = reinterpret_cast<const float4*>(fsh);
            float a = 0.f;
            #pragma unroll
            for (int j = 0; j < 2; j++) {
                float4 cv = crow[lane * 2 + j];
                float4 fq = frow[lane * 2 + j];
                a += fq.x * cv.x + fq.y * cv.y + fq.z * cv.z + fq.w * cv.w;
            }
            #pragma unroll
            for (int m = 16; m; m >>= 1) a += __shfl_xor_sync(0xffffffffu, a, m);
            if (lane == 0) {
                unsigned long long kk = mkkey(a, code);
                if (kk > lb) lb = kk;
            }
        }
    }
    if (lane == 0 && lb) atomicMax(&bestk, lb);
    __syncthreads();

    unsigned code = 0xFFFFFFFFu - (unsigned)(bestk & 0xFFFFFFFFull);
    float v = cb[(size_t)code * 256 + tid];
    __nv_bfloat16 h = __float2bfloat16(v);
    qh[(size_t)row * 256 + tid] = h;
    ql[(size_t)row * 256 + tid] = __float2bfloat16(v - __bfloat162float(h));
    if (tid == 0 && idx_out) idx_out[row] = (float)code;
}

// ---------------- deconv3: direct, Cout=3, NHWC in -> NCHW out --------------
__global__ void deconv3_k(const float* __restrict__ in, const float* __restrict__ w,
                          const float* __restrict__ b, float* __restrict__ out)
{
    __shared__ float ws[3 * 64 * 16];
    for (int i = threadIdx.x; i < 3072; i += THREADS) ws[i] = w[i];
    __syncthreads();
    int gid = blockIdx.x * THREADS + threadIdx.x;
    int ow = gid & 255;
    int oh = (gid >> 8) & 255;
    int n  = gid >> 16;
    int ph = oh & 1, pw = ow & 1;
    int r = oh >> 1, c = ow >> 1;
    float a0 = b[0], a1 = b[1], a2 = b[2];
    #pragma unroll
    for (int th = 0; th < 2; th++) {
        int ih = r + th - 1 + ph;
        if ((unsigned)ih >= 128u) continue;
        int kh = 2 * th + ph;
        #pragma unroll
        for (int tw = 0; tw < 2; tw++) {
            int iw = c + tw - 1 + pw;
            if ((unsigned)iw >= 128u) continue;
            int kw = 2 * tw + pw;
            const float* xp = in + ((size_t)(n * 128 + ih) * 128 + iw) * 64;
            int wo = kh * 4 + kw;
            #pragma unroll
            for (int c4 = 0; c4 < 16; c4++) {
                float4 xv = *reinterpret_cast<const float4*>(xp + c4 * 4);
                int ci = c4 * 4;
                a0 += xv.x * ws[(0 * 64 + ci) * 16 + wo] + xv.y * ws[(0 * 64 + ci + 1) * 16 + wo]
                    + xv.z * ws[(0 * 64 + ci + 2) * 16 + wo] + xv.w * ws[(0 * 64 + ci + 3) * 16 + wo];
                a1 += xv.x * ws[(1 * 64 + ci) * 16 + wo] + xv.y * ws[(1 * 64 + ci + 1) * 16 + wo]
                    + xv.z * ws[(1 * 64 + ci + 2) * 16 + wo] + xv.w * ws[(1 * 64 + ci + 3) * 16 + wo];
                a2 += xv.x * ws[(2 * 64 + ci) * 16 + wo] + xv.y * ws[(2 * 64 + ci + 1) * 16 + wo]
                    + xv.z * ws[(2 * 64 + ci + 2) * 16 + wo] + xv.w * ws[(2 * 64 + ci + 3) * 16 + wo];
            }
        }
    }
    size_t p = (size_t)n * 3 * 65536 + (size_t)oh * 256 + ow;
    out[p] = a0;
    out[p + 65536] = a1;
    out[p + 2 * 65536] = a2;
}

// ---------------------------------------------------------------------------
extern "C" void kernel_launch(void* const* d_in, const int* in_sizes, int n_in,
                              void* d_out, int out_size)
{
    const float* x   = (const float*)d_in[0];
    const float* ew1 = (const float*)d_in[1];
    const float* eb1 = (const float*)d_in[2];
    const float* ew2 = (const float*)d_in[3];
    const float* eb2 = (const float*)d_in[4];
    const float* ew3 = (const float*)d_in[5];
    const float* eb3 = (const float*)d_in[6];
    const float* cb  = (const float*)d_in[7];
    const float* dw1 = (const float*)d_in[8];
    const float* db1 = (const float*)d_in[9];
    const float* dw2 = (const float*)d_in[10];
    const float* db2 = (const float*)d_in[11];
    const float* dw3 = (const float*)d_in[12];
    const float* db3 = (const float*)d_in[13];
    float* out = (float*)d_out;

    float *h1, *h2, *feat, *d2, *wp;
    __nv_bfloat16 *cbb, *fb, *qh, *ql, *xh, *xl;
    unsigned long long* grp;
    cudaGetSymbolAddress((void**)&h1,   g_h1);
    cudaGetSymbolAddress((void**)&h2,   g_h2);
    cudaGetSymbolAddress((void**)&feat, g_feat);
    cudaGetSymbolAddress((void**)&d2,   g_d2);
    cudaGetSymbolAddress((void**)&wp,   g_wp);
    cudaGetSymbolAddress((void**)&cbb,  g_cbb);
    cudaGetSymbolAddress((void**)&fb,   g_fb);
    cudaGetSymbolAddress((void**)&grp,  g_grp);
    cudaGetSymbolAddress((void**)&qh,   g_qh);
    cudaGetSymbolAddress((void**)&ql,   g_ql);
    cudaGetSymbolAddress((void**)&xh,   g_xh);
    cudaGetSymbolAddress((void**)&xl,   g_xl);

    float* wp3 = wp;                                           // 524288 f
    float* wp2 = wp + 524288;                                  // 131072 f
    __nv_bfloat16* wh1 = (__nv_bfloat16*)(wp + 655360);        // 524288 bf
    __nv_bfloat16* wl1 = (__nv_bfloat16*)(wp + 917504);        // 524288 bf
    __nv_bfloat16* wh2 = (__nv_bfloat16*)(wp + 1179648);       // 131072 bf
    __nv_bfloat16* wl2 = (__nv_bfloat16*)(wp + 1245184);       // 131072 bf

    const int RECON = 16 * 3 * 256 * 256;
    float* idx_out = (out_size >= RECON + 16384) ? (out + RECON) : nullptr;

    // 1: conv1 (4 co/thread, bit-exact fp32) + ALL prep
    conv1_prep_k<<<16384 + 512 + 2048 + 2048 + 2048 + 512, THREADS>>>(
        x, ew1, eb1, h1, ew2, wp2, ew3, wp3, cb, cbb, dw1, wh1, wl1, dw2, wh2, wl2);

    // 2-3: encoder GEMMs (fp32 exact — argmax indices must match reference)
    gemm_k<6, 6, 0><<<dim3(1, 512), THREADS>>>(h1, wp2, 65536, 128, 1024, eb2, h2, nullptr);
    gemm_k<7, 5, 2><<<dim3(2, 128), THREADS>>>(h2, wp3, 16384, 256, 2048, eb3, feat, fb);

    // 4-5: quantize
    scores_hmma_k<<<dim3(64, 128), THREADS>>>(fb, cbb, grp);
    rescue_k<<<16384, THREADS>>>(grp, feat, cb, qh, ql, idx_out);

    // 6-7: decoder split-bf16 HMMA deconvs (128-row tiles, 3-term)
    {
        constexpr int SMEM1 = 2 * (2 * 128 * 40 * 2 + 2 * 128 * 40 * 2);   // 81920
        cudaFuncSetAttribute((const void*)deconv_hmma_k<8, 5, 128, 32, true>,
                             cudaFuncAttributeMaxDynamicSharedMemorySize, SMEM1);
        deconv_hmma_k<8, 5, 128, 32, true><<<dim3(128, 1, 4), THREADS, SMEM1>>>(
            qh, ql, wh1, wl1, db1, nullptr, xh, xl);
    }
    {
        constexpr int SMEM2 = 2 * (2 * 128 * 40 * 2 + 2 * 64 * 40 * 2);    // 61440
        cudaFuncSetAttribute((const void*)deconv_hmma_k<7, 6, 64, 16, false>,
                             cudaFuncAttributeMaxDynamicSharedMemorySize, SMEM2);
        deconv_hmma_k<7, 6, 64, 16, false><<<dim3(512, 1, 4), THREADS, SMEM2>>>(
            xh, xl, wh2, wl2, db2, d2, nullptr, nullptr);
    }

    // 8: final deconv
    deconv3_k<<<4096, THREADS>>>(d2, dw3, db3, out);
}